// round 1
// baseline (speedup 1.0000x reference)
#include <cuda_runtime.h>
#include <cuda_bf16.h>
#include <math.h>

// Problem dims (fixed by setup_inputs)
#define NN 16384
#define DD 1024
#define KK 32
#define LL 16
#define LOG2PI_F 1.8378770664093453f

// ---------------- device scratch (no cudaMalloc allowed) ----------------
__device__ float gW [DD][1088];        // [iD*MU(32) | B(512) | A(512) | pad(32)]
__device__ float gW2[DD][64];          // [iD(32) | ones(1) | pad]
__device__ float gS [NN][64];          // x^2 @ W2 : cols 0..31 = sq, 32 = ||x||^2
__device__ float gC [NN][1088];        // x @ W
__device__ float gM2[NN][576];         // [r(32) | r*P(512) | r*x2(32)]
__device__ float gSiAiRaw[DD][576];    // x^T @ M2
__device__ float gSiAi2[KK][DD][LL];
__device__ float gmu[KK][DD];
__device__ float giL  [KK][LL][LL];
__device__ float gInvM[KK][LL][LL];
__device__ float gbmu [KK][LL];
__device__ float gG   [KK][LL];
__device__ float gconst[KK];
__device__ float gck[KK];
__device__ float gs2[KK];
__device__ float grsum[KK];
__device__ float grx2[KK];

// ---------------- helpers ----------------
__device__ __forceinline__ float block_reduce_sum(float v, float* sbuf) {
    int t = threadIdx.x;
    sbuf[t] = v; __syncthreads();
    for (int s = 128; s > 0; s >>= 1) {
        if (t < s) sbuf[t] += sbuf[t + s];
        __syncthreads();
    }
    float r = sbuf[0];
    __syncthreads();
    return r;
}

// 16x16 Gauss-Jordan with partial pivoting. aug[16][32], right half -> inverse.
// Requires 256 threads. slogdet (shared) must be zeroed by caller if used.
__device__ void block_invert16(float aug[16][32], float* slogdet, float* sfac, int* spiv) {
    int t = threadIdx.x;
    int r = t >> 4, c = t & 15;
    for (int p = 0; p < 16; ++p) {
        __syncthreads();
        if (t == 0) {
            int best = p; float bv = fabsf(aug[p][p]);
            for (int rr = p + 1; rr < 16; ++rr) {
                float v = fabsf(aug[rr][p]);
                if (v > bv) { bv = v; best = rr; }
            }
            *spiv = best;
            if (slogdet) *slogdet += logf(fmaxf(bv, 1e-30f));
        }
        __syncthreads();
        int pr = *spiv;
        if (pr != p && t < 32) { float tmp = aug[p][t]; aug[p][t] = aug[pr][t]; aug[pr][t] = tmp; }
        __syncthreads();
        if (t < 32) {
            float val = aug[p][t];
            float pv  = aug[p][p];
            __syncwarp();
            aug[p][t] = val / pv;
        }
        __syncthreads();
        if (c == 0) sfac[r] = aug[r][p];
        __syncthreads();
        if (r != p) {
            float f = sfac[r];
            aug[r][c]      -= f * aug[p][c];
            aug[r][c + 16] -= f * aug[p][c + 16];
        }
    }
    __syncthreads();
}

// ---------------- kernel 0: zero scratch ----------------
__global__ void zero_kernel() {
    size_t i0 = (size_t)blockIdx.x * blockDim.x + threadIdx.x;
    size_t str = (size_t)gridDim.x * blockDim.x;
    float* p;
    p = &gW[0][0];       for (size_t i = i0; i < (size_t)DD * 1088; i += str) p[i] = 0.f;
    p = &gW2[0][0];      for (size_t i = i0; i < (size_t)DD * 64;   i += str) p[i] = 0.f;
    p = &gS[0][0];       for (size_t i = i0; i < (size_t)NN * 64;   i += str) p[i] = 0.f;
    p = &gSiAiRaw[0][0]; for (size_t i = i0; i < (size_t)DD * 576;  i += str) p[i] = 0.f;
    if (i0 < KK) { grsum[i0] = 0.f; grx2[i0] = 0.f; }
    p = &gG[0][0]; if (i0 < KK * LL) p[i0] = 0.f;
}

// ---------------- kernel 1: per-k setup ----------------
__global__ void setup_kernel(const float* __restrict__ MU, const float* __restrict__ A,
                             const float* __restrict__ log_D, const float* __restrict__ PI_logits) {
    int k = blockIdx.x, t = threadIdx.x;
    __shared__ float sred[256];
    __shared__ float sPIk;
    if (t == 0) {
        float mx = -1e30f;
        for (int j = 0; j < KK; ++j) mx = fmaxf(mx, PI_logits[j]);
        float s = 0.f;
        for (int j = 0; j < KK; ++j) s += expf(PI_logits[j] - mx);
        sPIk = expf(PI_logits[k] - mx) / s;
    }
    // phase 0: per-d scalars
    float constAcc = 0.f, sumLD = 0.f;
    for (int d = t; d < DD; d += 256) {
        float ld = log_D[k * DD + d];
        float iD = expf(-ld);
        float mu = MU[k * DD + d];
        gW2[d][k] = iD;
        if (k == 0) gW2[d][32] = 1.f;
        gW[d][k] = iD * mu;
        constAcc += iD * mu * mu;
        sumLD += ld;
    }
    __syncthreads();
    // phase 1: B/A columns of W + bmu partials
    float bmuAcc = 0.f;
    {
        int l = t & 15;
        for (int d = t >> 4; d < DD; d += 16) {
            float a = A[((size_t)k * DD + d) * LL + l];
            float iD = gW2[d][k];
            float b = iD * a;
            gW[d][32  + k * 16 + l] = b;
            gW[d][544 + k * 16 + l] = a;
            bmuAcc += MU[k * DD + d] * b;
        }
    }
    // phase 2: L = I + A^T(iD*A), ATA
    int li = t >> 4, mi = t & 15;
    float Lacc = 0.f, ATAacc = 0.f;
    __shared__ float sA[16][16];
    __shared__ float siD[16];
    for (int d0 = 0; d0 < DD; d0 += 16) {
        __syncthreads();
        sA[li][mi] = A[((size_t)k * DD + d0 + li) * LL + mi];
        if (t < 16) siD[t] = gW2[d0 + t][k];
        __syncthreads();
        #pragma unroll
        for (int dd = 0; dd < 16; ++dd) {
            float al = sA[dd][li], am = sA[dd][mi];
            ATAacc += al * am;
            Lacc   += al * siD[dd] * am;
        }
    }
    float constK = block_reduce_sum(constAcc, sred);
    float sumLDK = block_reduce_sum(sumLD, sred);
    __shared__ float sbm[16][17];
    sbm[t & 15][t >> 4] = bmuAcc;
    __syncthreads();
    if (t < 16) {
        float s = 0.f;
        for (int g = 0; g < 16; ++g) s += sbm[t][g];
        gbmu[k][t] = s;
    }
    __shared__ float aug[16][32];
    __shared__ float sfac[16];
    __shared__ int spiv;
    __shared__ float slogdet;
    if (t == 0) slogdet = 0.f;
    __syncthreads();
    aug[li][mi]      = Lacc + (li == mi ? 1.f : 0.f);
    aug[li][16 + mi] = (li == mi ? 1.f : 0.f);
    block_invert16(aug, &slogdet, sfac, &spiv);
    giL[k][li][mi] = aug[li][16 + mi];
    float logdetL = slogdet;
    __syncthreads();
    float s2 = expf(log_D[k * DD]);
    aug[li][mi]      = ATAacc + (li == mi ? s2 : 0.f);
    aug[li][16 + mi] = (li == mi ? 1.f : 0.f);
    block_invert16(aug, nullptr, sfac, &spiv);
    gInvM[k][li][mi] = aug[li][16 + mi];
    if (t == 0) {
        gconst[k] = constK;
        gck[k] = sPIk - 0.5f * ((float)DD * LOG2PI_F + logdetL + sumLDK);
        gs2[k] = s2;
    }
}

// ---------------- GEMM bodies ----------------
// C[M,ldc] = op(X) @ W ;  X row-major [*,1024] (A-operand, transposed on load)
template<bool SQ, bool ATOMIC>
__device__ __forceinline__ void gemm_xw_body(
    const float* __restrict__ X, const float* __restrict__ W, float* __restrict__ C,
    int ldw, int ldc, int kBeg, int kEnd)
{
    __shared__ float As[16][128];
    __shared__ float Bs[16][64];
    const int t = threadIdx.x;
    const int m0 = blockIdx.x * 128;
    const int n0 = blockIdx.y * 64;
    const int tx = t & 15, ty = t >> 4;
    float acc[8][4] = {};
    for (int kk = kBeg; kk < kEnd; kk += 16) {
        #pragma unroll
        for (int i = 0; i < 2; ++i) {
            int idx = t + i * 256;
            int row = idx >> 2, c4 = idx & 3;
            float4 v = *(const float4*)(X + (size_t)(m0 + row) * DD + kk + c4 * 4);
            if (SQ) { v.x *= v.x; v.y *= v.y; v.z *= v.z; v.w *= v.w; }
            As[c4 * 4 + 0][row] = v.x;
            As[c4 * 4 + 1][row] = v.y;
            As[c4 * 4 + 2][row] = v.z;
            As[c4 * 4 + 3][row] = v.w;
        }
        {
            int row = t >> 4, c4 = t & 15;
            *(float4*)(&Bs[row][c4 * 4]) = *(const float4*)(W + (size_t)(kk + row) * ldw + n0 + c4 * 4);
        }
        __syncthreads();
        #pragma unroll
        for (int kq = 0; kq < 16; ++kq) {
            float4 a0 = *(const float4*)&As[kq][ty * 8];
            float4 a1 = *(const float4*)&As[kq][ty * 8 + 4];
            float4 b  = *(const float4*)&Bs[kq][tx * 4];
            float a[8] = {a0.x, a0.y, a0.z, a0.w, a1.x, a1.y, a1.z, a1.w};
            float bb[4] = {b.x, b.y, b.z, b.w};
            #pragma unroll
            for (int i = 0; i < 8; ++i)
                #pragma unroll
                for (int j = 0; j < 4; ++j)
                    acc[i][j] += a[i] * bb[j];
        }
        __syncthreads();
    }
    #pragma unroll
    for (int i = 0; i < 8; ++i) {
        float* cp = C + (size_t)(m0 + ty * 8 + i) * ldc + n0 + tx * 4;
        if (ATOMIC) {
            atomicAdd(cp + 0, acc[i][0]); atomicAdd(cp + 1, acc[i][1]);
            atomicAdd(cp + 2, acc[i][2]); atomicAdd(cp + 3, acc[i][3]);
        } else {
            float4 v = make_float4(acc[i][0], acc[i][1], acc[i][2], acc[i][3]);
            *(float4*)cp = v;
        }
    }
}

__global__ void __launch_bounds__(256) gemm_b1(const float* __restrict__ x) {
    int kb = blockIdx.z * 128;
    gemm_xw_body<true, true>(x, &gW2[0][0], &gS[0][0], 64, 64, kb, kb + 128);
}
__global__ void __launch_bounds__(256) gemm_b2(const float* __restrict__ x) {
    gemm_xw_body<false, false>(x, &gW[0][0], &gC[0][0], 1088, 1088, 0, DD);
}

// gSiAiRaw += x^T @ gM2   (both K-major; split over N via blockIdx.z)
__global__ void __launch_bounds__(256) gemm_d(const float* __restrict__ X) {
    __shared__ float As[16][128];
    __shared__ float Bs[16][64];
    const int t = threadIdx.x;
    const int m0 = blockIdx.x * 128;      // d
    const int n0 = blockIdx.y * 64;       // M2 col
    const int kBeg = blockIdx.z * 2048, kEnd = kBeg + 2048;
    const int tx = t & 15, ty = t >> 4;
    float acc[8][4] = {};
    for (int kk = kBeg; kk < kEnd; kk += 16) {
        #pragma unroll
        for (int i = 0; i < 2; ++i) {
            int idx = t + i * 256;
            int row = idx >> 5, c = idx & 31;
            *(float4*)&As[row][c * 4] = *(const float4*)(X + (size_t)(kk + row) * DD + m0 + c * 4);
        }
        {
            int row = t >> 4, c4 = t & 15;
            *(float4*)&Bs[row][c4 * 4] = *(const float4*)(&gM2[kk + row][n0 + c4 * 4]);
        }
        __syncthreads();
        #pragma unroll
        for (int kq = 0; kq < 16; ++kq) {
            float4 a0 = *(const float4*)&As[kq][ty * 8];
            float4 a1 = *(const float4*)&As[kq][ty * 8 + 4];
            float4 b  = *(const float4*)&Bs[kq][tx * 4];
            float a[8] = {a0.x, a0.y, a0.z, a0.w, a1.x, a1.y, a1.z, a1.w};
            float bb[4] = {b.x, b.y, b.z, b.w};
            #pragma unroll
            for (int i = 0; i < 8; ++i)
                #pragma unroll
                for (int j = 0; j < 4; ++j)
                    acc[i][j] += a[i] * bb[j];
        }
        __syncthreads();
    }
    #pragma unroll
    for (int i = 0; i < 8; ++i) {
        float* cp = &gSiAiRaw[m0 + ty * 8 + i][n0 + tx * 4];
        atomicAdd(cp + 0, acc[i][0]); atomicAdd(cp + 1, acc[i][1]);
        atomicAdd(cp + 2, acc[i][2]); atomicAdd(cp + 3, acc[i][3]);
    }
}

// ---------------- E-step epilogue: logits -> r, build M2 ----------------
__global__ void __launch_bounds__(256) estep_epilogue() {
    __shared__ float siLs[KK * 272];       // [k][gl*17+m], padded
    __shared__ float sbmu_[KK][LL];
    __shared__ float sconst_[KK];
    __shared__ float sck_[KK];
    __shared__ float sll[8][32];
    int t = threadIdx.x;
    for (int idx = t; idx < KK * 256; idx += 256) {
        int kk = idx >> 8, rem = idx & 255;
        siLs[kk * 272 + (rem >> 4) * 17 + (rem & 15)] = (&giL[0][0][0])[idx];
    }
    for (int idx = t; idx < KK * LL; idx += 256) (&sbmu_[0][0])[idx] = (&gbmu[0][0])[idx];
    if (t < KK) { sconst_[t] = gconst[t]; sck_[t] = gck[t]; }
    __syncthreads();

    int warp = t >> 5, lane = t & 31;
    int n = blockIdx.x * 8 + warp;
    const float* Crow = &gC[n][0];
    float x2 = gS[n][32];
    #pragma unroll 1
    for (int it = 0; it < 16; ++it) {
        int k = it * 2 + (lane >> 4);
        int gl = lane & 15;
        float yv = Crow[32 + k * 16 + gl] - sbmu_[k][gl];
        float z = 0.f;
        const float* ilr = &siLs[k * 272 + gl * 17];
        #pragma unroll
        for (int m = 0; m < 16; ++m) {
            float ym = __shfl_sync(0xffffffffu, yv, (lane & 16) | m);
            z += ilr[m] * ym;
        }
        float t2 = z * yv;
        #pragma unroll
        for (int off = 8; off > 0; off >>= 1) t2 += __shfl_xor_sync(0xffffffffu, t2, off);
        if (gl == 0) {
            float term1 = gS[n][k] - 2.f * Crow[k] + sconst_[k];
            sll[warp][k] = sck_[k] - 0.5f * term1 + 0.5f * t2;
        }
    }
    __syncwarp();
    float llk = sll[warp][lane];
    float mx = llk;
    #pragma unroll
    for (int off = 16; off > 0; off >>= 1) mx = fmaxf(mx, __shfl_xor_sync(0xffffffffu, mx, off));
    float e = expf(llk - mx);
    float s = e;
    #pragma unroll
    for (int off = 16; off > 0; off >>= 1) s += __shfl_xor_sync(0xffffffffu, s, off);
    float r = e / s;
    float* Mrow = &gM2[n][0];
    Mrow[lane] = r;
    Mrow[544 + lane] = r * x2;
    #pragma unroll
    for (int it = 0; it < 16; ++it) {
        int j = it * 32 + lane;
        float rk = __shfl_sync(0xffffffffu, r, j >> 4);
        Mrow[32 + j] = rk * Crow[544 + j];
    }
}

// ---------------- column sums of M2 -> r_sum, G, rx2 ----------------
__global__ void __launch_bounds__(256) colsum_kernel() {
    int t = threadIdx.x;
    int col = blockIdx.x * 64 + (t & 63);
    int sub = t >> 6;
    int rowEnd = (blockIdx.y + 1) * 2048;
    float acc = 0.f;
    for (int row = blockIdx.y * 2048 + sub; row < rowEnd; row += 4)
        acc += gM2[row][col];
    __shared__ float sb[4][64];
    sb[sub][t & 63] = acc;
    __syncthreads();
    if (t < 64) {
        float s = sb[0][t] + sb[1][t] + sb[2][t] + sb[3][t];
        int c = blockIdx.x * 64 + t;
        if (c < 32)       atomicAdd(&grsum[c], s);
        else if (c < 544) atomicAdd(&gG[0][0] + (c - 32), s);
        else              atomicAdd(&grx2[c - 544], s);
    }
}

// ---------------- finalize mu + SiAi ----------------
__global__ void __launch_bounds__(256) finalize_kernel(float* __restrict__ outMu) {
    int idx = blockIdx.x * 256 + threadIdx.x;   // K*D = 32768
    int k = idx >> 10, d = idx & 1023;
    float rs = grsum[k];
    float inv = 1.f / rs;
    float mu = gSiAiRaw[d][k] * inv;
    gmu[k][d] = mu;
    outMu[idx] = mu;
    #pragma unroll
    for (int l = 0; l < 16; ++l)
        gSiAi2[k][d][l] = (gSiAiRaw[d][32 + k * 16 + l] - mu * gG[k][l]) * inv;
}

// ---------------- per-k M-step ----------------
__global__ void __launch_bounds__(256) mstep_kernel(const float* __restrict__ A,
                                                    float* __restrict__ outA,
                                                    float* __restrict__ outLogD,
                                                    float* __restrict__ outPI) {
    int k = blockIdx.x, t = threadIdx.x;
    int li = t >> 4, mi = t & 15;
    __shared__ float sS[16][16];
    __shared__ float sAs[16][16];
    float acc = 0.f;   // ATSiAi[li][mi]
    for (int d0 = 0; d0 < DD; d0 += 16) {
        __syncthreads();
        sAs[li][mi] = A[((size_t)k * DD + d0 + li) * LL + mi];
        sS [li][mi] = gSiAi2[k][d0 + li][mi];
        __syncthreads();
        #pragma unroll
        for (int dd = 0; dd < 16; ++dd) acc += sAs[dd][li] * sS[dd][mi];
    }
    __shared__ float sATS[16][16];
    __shared__ float siM[16][16];
    __syncthreads();
    sATS[li][mi] = acc;
    siM[li][mi] = gInvM[k][li][mi];
    __syncthreads();
    float Tv = 0.f;
    #pragma unroll
    for (int j = 0; j < 16; ++j) Tv += siM[li][j] * sATS[j][mi];
    __shared__ float aug[16][32];
    __shared__ float sfac[16];
    __shared__ int spiv;
    aug[li][mi]      = Tv + (li == mi ? gs2[k] : 0.f);
    aug[li][16 + mi] = (li == mi ? 1.f : 0.f);
    block_invert16(aug, nullptr, sfac, &spiv);
    __shared__ float sW2[16][16];
    sW2[li][mi] = aug[li][16 + mi];
    __syncthreads();
    float t1acc = 0.f;
    for (int d0 = 0; d0 < DD; d0 += 16) {
        __syncthreads();
        sS[li][mi] = gSiAi2[k][d0 + li][mi];
        __syncthreads();
        float an = 0.f, sim = 0.f;
        #pragma unroll
        for (int m = 0; m < 16; ++m) {
            float sv = sS[li][m];
            an  += sv * sW2[m][mi];
            sim += sv * siM[m][mi];
        }
        outA[((size_t)k * DD + d0 + li) * LL + mi] = an;
        t1acc += an * sim;
    }
    float msq = 0.f;
    for (int d = t; d < DD; d += 256) { float m = gmu[k][d]; msq += m * m; }
    __shared__ float sred[256];
    float t1   = block_reduce_sum(t1acc, sred);
    float msqs = block_reduce_sum(msq, sred);
    __shared__ float sld;
    if (t == 0) {
        float rs = grsum[k];
        float traceS = (grx2[k] - rs * msqs) / rs;
        float sig2 = (traceS - t1) / (float)DD;
        sld = logf(sig2);
        float tot = 0.f;
        for (int j = 0; j < KK; ++j) tot += grsum[j];
        outPI[k] = logf(grsum[k] / tot);
    }
    __syncthreads();
    float ldv = sld;
    for (int d = t; d < DD; d += 256) outLogD[k * DD + d] = ldv;
}

// ---------------- launch ----------------
extern "C" void kernel_launch(void* const* d_in, const int* in_sizes, int n_in,
                              void* d_out, int out_size) {
    const float* x   = (const float*)d_in[0];
    const float* MU  = (const float*)d_in[1];
    const float* A   = (const float*)d_in[2];
    const float* lD  = (const float*)d_in[3];
    const float* PIl = (const float*)d_in[4];
    float* out = (float*)d_out;
    float* outMu   = out;                       // [32,1024]
    float* outA    = out + KK * DD;             // [32,1024,16]
    float* outLogD = out + KK * DD + KK * DD * LL;
    float* outPI   = out + KK * DD + KK * DD * LL + KK * DD;

    zero_kernel<<<1024, 256>>>();
    setup_kernel<<<KK, 256>>>(MU, A, lD, PIl);
    gemm_b1<<<dim3(NN / 128, 1, 8), 256>>>(x);
    gemm_b2<<<dim3(NN / 128, 1088 / 64, 1), 256>>>(x);
    estep_epilogue<<<NN / 8, 256>>>();
    colsum_kernel<<<dim3(576 / 64, 8), 256>>>();
    gemm_d<<<dim3(DD / 128, 576 / 64, 8), 256>>>(x);
    finalize_kernel<<<(KK * DD) / 256, 256>>>(outMu);
    mstep_kernel<<<KK, 256>>>(A, outA, outLogD, outPI);
}

// round 2
// speedup vs baseline: 1.2412x; 1.2412x over previous
#include <cuda_runtime.h>
#include <cuda_bf16.h>
#include <math.h>

// Problem dims (fixed by setup_inputs)
#define NN 16384
#define DD 1024
#define KK 32
#define LL 16
#define WPAD 640              // padded width for [MU(32) | A(512) | pad]
#define M2W 640               // padded width for [r(32) | r*q(512) | r*x2(32) | pad]
#define LOG2PI_F 1.8378770664093453f

// ---------------- device scratch (no cudaMalloc allowed) ----------------
__device__ float gW [DD][WPAD];        // [MU(32) | A(512) | zero pad]
__device__ float gC [NN][WPAD];        // x @ W
__device__ float gM2[NN][M2W];         // [r | r*q | r*x2 | zero pad]
__device__ float gX2[NN];              // ||x_n||^2
__device__ float gSiAiRaw[DD][M2W];    // x^T @ M2
__device__ float gSiAi2[KK][DD][LL];
__device__ float gmu[KK][DD];
__device__ float giL  [KK][LL][LL];
__device__ float gInvM[KK][LL][LL];
__device__ float gbmu [KK][LL];        // MU_k . A_col_l
__device__ float gG   [KK][LL];
__device__ float gmuSq[KK];
__device__ float giD [KK];
__device__ float gck[KK];
__device__ float gs2[KK];
__device__ float grsum[KK];
__device__ float grx2[KK];

// ---------------- helpers ----------------
__device__ __forceinline__ float block_reduce_sum(float v, float* sbuf) {
    int t = threadIdx.x;
    sbuf[t] = v; __syncthreads();
    for (int s = 128; s > 0; s >>= 1) {
        if (t < s) sbuf[t] += sbuf[t + s];
        __syncthreads();
    }
    float r = sbuf[0];
    __syncthreads();
    return r;
}

// 16x16 Gauss-Jordan with partial pivoting. aug[16][32], right half -> inverse.
__device__ void block_invert16(float aug[16][32], float* slogdet, float* sfac, int* spiv) {
    int t = threadIdx.x;
    int r = t >> 4, c = t & 15;
    for (int p = 0; p < 16; ++p) {
        __syncthreads();
        if (t == 0) {
            int best = p; float bv = fabsf(aug[p][p]);
            for (int rr = p + 1; rr < 16; ++rr) {
                float v = fabsf(aug[rr][p]);
                if (v > bv) { bv = v; best = rr; }
            }
            *spiv = best;
            if (slogdet) *slogdet += logf(fmaxf(bv, 1e-30f));
        }
        __syncthreads();
        int pr = *spiv;
        if (pr != p && t < 32) { float tmp = aug[p][t]; aug[p][t] = aug[pr][t]; aug[pr][t] = tmp; }
        __syncthreads();
        if (t < 32) {
            float val = aug[p][t];
            float pv  = aug[p][p];
            __syncwarp();
            aug[p][t] = val / pv;
        }
        __syncthreads();
        if (c == 0) sfac[r] = aug[r][p];
        __syncthreads();
        if (r != p) {
            float f = sfac[r];
            aug[r][c]      -= f * aug[p][c];
            aug[r][c + 16] -= f * aug[p][c + 16];
        }
    }
    __syncthreads();
}

// ---------------- kernel 0: zero scratch ----------------
__global__ void zero_kernel() {
    size_t i0 = (size_t)blockIdx.x * blockDim.x + threadIdx.x;
    size_t str = (size_t)gridDim.x * blockDim.x;
    float* p;
    p = &gW[0][0];       for (size_t i = i0; i < (size_t)DD * WPAD; i += str) p[i] = 0.f;
    p = &gSiAiRaw[0][0]; for (size_t i = i0; i < (size_t)DD * M2W; i += str) p[i] = 0.f;
    if (i0 < KK) { grsum[i0] = 0.f; grx2[i0] = 0.f; }
    p = &gG[0][0]; if (i0 < KK * LL) p[i0] = 0.f;
}

// ---------------- x2 kernel: row sums of x^2 ----------------
__global__ void __launch_bounds__(256) x2_kernel(const float* __restrict__ x) {
    int warp = threadIdx.x >> 5, lane = threadIdx.x & 31;
    int n = blockIdx.x * 8 + warp;
    const float4* xr = (const float4*)(x + (size_t)n * DD);
    float s = 0.f;
    #pragma unroll
    for (int c = lane; c < 256; c += 32) {
        float4 v = xr[c];
        s += v.x * v.x + v.y * v.y + v.z * v.z + v.w * v.w;
    }
    #pragma unroll
    for (int off = 16; off > 0; off >>= 1) s += __shfl_xor_sync(0xffffffffu, s, off);
    if (lane == 0) gX2[n] = s;
}

// ---------------- kernel 1: per-k setup (isotropic iD) ----------------
__global__ void setup_kernel(const float* __restrict__ MU, const float* __restrict__ A,
                             const float* __restrict__ log_D, const float* __restrict__ PI_logits) {
    int k = blockIdx.x, t = threadIdx.x;
    __shared__ float sred[256];
    __shared__ float sPIk;
    if (t == 0) {
        float mx = -1e30f;
        for (int j = 0; j < KK; ++j) mx = fmaxf(mx, PI_logits[j]);
        float s = 0.f;
        for (int j = 0; j < KK; ++j) s += expf(PI_logits[j] - mx);
        sPIk = expf(PI_logits[k] - mx) / s;
    }
    float ld0 = log_D[(size_t)k * DD];
    float iD = expf(-ld0);
    float s2 = expf(ld0);
    // phase 0: W col k = MU row k; muSq
    float muSqAcc = 0.f;
    for (int d = t; d < DD; d += 256) {
        float mu = MU[(size_t)k * DD + d];
        gW[d][k] = mu;
        muSqAcc += mu * mu;
    }
    // phase 1: A columns of W + bmuA partials
    float bmuAcc = 0.f;
    {
        int l = t & 15;
        for (int d = t >> 4; d < DD; d += 16) {
            float a = A[((size_t)k * DD + d) * LL + l];
            gW[d][32 + k * 16 + l] = a;
            bmuAcc += MU[(size_t)k * DD + d] * a;
        }
    }
    // phase 2: ATA
    int li = t >> 4, mi = t & 15;
    float ATAacc = 0.f;
    __shared__ float sA[16][16];
    for (int d0 = 0; d0 < DD; d0 += 16) {
        __syncthreads();
        sA[li][mi] = A[((size_t)k * DD + d0 + li) * LL + mi];
        __syncthreads();
        #pragma unroll
        for (int dd = 0; dd < 16; ++dd) ATAacc += sA[dd][li] * sA[dd][mi];
    }
    float muSqK = block_reduce_sum(muSqAcc, sred);
    __shared__ float sbm[16][17];
    sbm[t & 15][t >> 4] = bmuAcc;
    __syncthreads();
    if (t < 16) {
        float s = 0.f;
        for (int g = 0; g < 16; ++g) s += sbm[t][g];
        gbmu[k][t] = s;
    }
    __shared__ float aug[16][32];
    __shared__ float sfac[16];
    __shared__ int spiv;
    __shared__ float slogdet;
    if (t == 0) slogdet = 0.f;
    __syncthreads();
    // L = I + iD * A^T A
    aug[li][mi]      = iD * ATAacc + (li == mi ? 1.f : 0.f);
    aug[li][16 + mi] = (li == mi ? 1.f : 0.f);
    block_invert16(aug, &slogdet, sfac, &spiv);
    giL[k][li][mi] = aug[li][16 + mi];
    float logdetL = slogdet;
    __syncthreads();
    // inv_M = inv(A^T A + s2 I)
    aug[li][mi]      = ATAacc + (li == mi ? s2 : 0.f);
    aug[li][16 + mi] = (li == mi ? 1.f : 0.f);
    block_invert16(aug, nullptr, sfac, &spiv);
    gInvM[k][li][mi] = aug[li][16 + mi];
    if (t == 0) {
        gmuSq[k] = muSqK;
        giD[k] = iD;
        gs2[k] = s2;
        // log_det_Sigma = logdetL + d*log(s2)
        gck[k] = sPIk - 0.5f * ((float)DD * LOG2PI_F + logdetL + (float)DD * ld0);
    }
}

// ---------------- 128x128 double-buffered GEMM body ----------------
// C[m0..+128, n0..+128] (+)= op(Aop) @ Bop over k in [kBeg,kEnd)
// TRANSA: Aop row-major [M, lda], we read A^T-style (tile transposed on store)
// else:   Aop row-major [K, lda] read directly.
template<bool TRANSA, bool ATOMIC>
__device__ __forceinline__ void gemm128_body(
    const float* __restrict__ Aop, const float* __restrict__ Bop, float* __restrict__ C,
    int lda, int ldb, int ldc, int kBeg, int kEnd)
{
    __shared__ float As[2][16][132];
    __shared__ float Bs[2][16][132];
    const int t = threadIdx.x;
    const int m0 = blockIdx.x * 128;
    const int n0 = blockIdx.y * 128;
    const int tx = t & 15, ty = t >> 4;

    float4 pa[2], pb[2];
    float acc[8][8] = {};

    // --- load helpers ---
    // TRANSA slot s: m = s>>2 (0..127), kq = s&3 ; read Aop[(m0+m)*lda + kk + kq*4]
    // !TRANSA slot s: row = s>>5, c4 = s&31 ; read Aop[(kk+row)*lda + m0 + c4*4]
#define LOAD_A(kk)                                                              \
    {                                                                           \
        _Pragma("unroll")                                                       \
        for (int i = 0; i < 2; ++i) {                                           \
            int s = t + i * 256;                                                \
            if (TRANSA) {                                                       \
                int m = s >> 2, kq = s & 3;                                     \
                pa[i] = *(const float4*)(Aop + (size_t)(m0 + m) * lda + (kk) + kq * 4); \
            } else {                                                            \
                int row = s >> 5, c4 = s & 31;                                  \
                pa[i] = *(const float4*)(Aop + (size_t)((kk) + row) * lda + m0 + c4 * 4); \
            }                                                                   \
        }                                                                       \
    }
#define LOAD_B(kk)                                                              \
    {                                                                           \
        _Pragma("unroll")                                                       \
        for (int i = 0; i < 2; ++i) {                                           \
            int s = t + i * 256;                                                \
            int row = s >> 5, c4 = s & 31;                                      \
            pb[i] = *(const float4*)(Bop + (size_t)((kk) + row) * ldb + n0 + c4 * 4); \
        }                                                                       \
    }
#define STORE_AB(buf)                                                           \
    {                                                                           \
        _Pragma("unroll")                                                       \
        for (int i = 0; i < 2; ++i) {                                           \
            int s = t + i * 256;                                                \
            if (TRANSA) {                                                       \
                int m = s >> 2, kq = s & 3;                                     \
                As[buf][kq * 4 + 0][m] = pa[i].x;                               \
                As[buf][kq * 4 + 1][m] = pa[i].y;                               \
                As[buf][kq * 4 + 2][m] = pa[i].z;                               \
                As[buf][kq * 4 + 3][m] = pa[i].w;                               \
            } else {                                                            \
                int row = s >> 5, c4 = s & 31;                                  \
                *(float4*)&As[buf][row][c4 * 4] = pa[i];                        \
            }                                                                   \
            int row = s >> 5, c4 = s & 31;                                      \
            *(float4*)&Bs[buf][row][c4 * 4] = pb[i];                            \
        }                                                                       \
    }

    int nChunks = (kEnd - kBeg) >> 4;
    LOAD_A(kBeg); LOAD_B(kBeg);
    STORE_AB(0);
    __syncthreads();
    int buf = 0;
    for (int c = 1; c <= nChunks; ++c) {
        if (c < nChunks) { LOAD_A(kBeg + c * 16); LOAD_B(kBeg + c * 16); }
        #pragma unroll
        for (int kq = 0; kq < 16; ++kq) {
            float a[8], b[8];
            *(float4*)&a[0] = *(const float4*)&As[buf][kq][ty * 8];
            *(float4*)&a[4] = *(const float4*)&As[buf][kq][ty * 8 + 4];
            *(float4*)&b[0] = *(const float4*)&Bs[buf][kq][tx * 8];
            *(float4*)&b[4] = *(const float4*)&Bs[buf][kq][tx * 8 + 4];
            #pragma unroll
            for (int i = 0; i < 8; ++i)
                #pragma unroll
                for (int j = 0; j < 8; ++j)
                    acc[i][j] += a[i] * b[j];
        }
        if (c < nChunks) {
            STORE_AB(buf ^ 1);
            __syncthreads();
            buf ^= 1;
        }
    }
    #pragma unroll
    for (int i = 0; i < 8; ++i) {
        float* cp = C + (size_t)(m0 + ty * 8 + i) * ldc + n0 + tx * 8;
        if (ATOMIC) {
            #pragma unroll
            for (int j = 0; j < 8; ++j) atomicAdd(cp + j, acc[i][j]);
        } else {
            *(float4*)cp       = make_float4(acc[i][0], acc[i][1], acc[i][2], acc[i][3]);
            *(float4*)(cp + 4) = make_float4(acc[i][4], acc[i][5], acc[i][6], acc[i][7]);
        }
    }
#undef LOAD_A
#undef LOAD_B
#undef STORE_AB
}

__global__ void __launch_bounds__(256, 2) gemm_b2(const float* __restrict__ x) {
    gemm128_body<true, false>(x, &gW[0][0], &gC[0][0], DD, WPAD, WPAD, 0, DD);
}
__global__ void __launch_bounds__(256, 2) gemm_d(const float* __restrict__ x) {
    int kb = blockIdx.z * 2048;
    gemm128_body<false, true>(x, &gM2[0][0], &gSiAiRaw[0][0], DD, M2W, M2W, kb, kb + 2048);
}

// ---------------- E-step epilogue: logits -> r, build M2 ----------------
__global__ void __launch_bounds__(256) estep_epilogue() {
    __shared__ float siLs[KK * 272];       // [k][gl*17+m], padded
    __shared__ float sbmu_[KK][LL];
    __shared__ float smuSq_[KK];
    __shared__ float siD_[KK];
    __shared__ float sck_[KK];
    __shared__ float sll[8][32];
    int t = threadIdx.x;
    for (int idx = t; idx < KK * 256; idx += 256) {
        int kk = idx >> 8, rem = idx & 255;
        siLs[kk * 272 + (rem >> 4) * 17 + (rem & 15)] = (&giL[0][0][0])[idx];
    }
    for (int idx = t; idx < KK * LL; idx += 256) (&sbmu_[0][0])[idx] = (&gbmu[0][0])[idx];
    if (t < KK) { smuSq_[t] = gmuSq[t]; sck_[t] = gck[t]; siD_[t] = giD[t]; }
    __syncthreads();

    int warp = t >> 5, lane = t & 31;
    int n = blockIdx.x * 8 + warp;
    const float* Crow = &gC[n][0];
    float x2 = gX2[n];
    #pragma unroll 1
    for (int it = 0; it < 16; ++it) {
        int k = it * 2 + (lane >> 4);
        int gl = lane & 15;
        float yv = Crow[32 + k * 16 + gl] - sbmu_[k][gl];   // q - bmuA (unscaled)
        float z = 0.f;
        const float* ilr = &siLs[k * 272 + gl * 17];
        #pragma unroll
        for (int m = 0; m < 16; ++m) {
            float ym = __shfl_sync(0xffffffffu, yv, (lane & 16) | m);
            z += ilr[m] * ym;
        }
        float t2 = z * yv;
        #pragma unroll
        for (int off = 8; off > 0; off >>= 1) t2 += __shfl_xor_sync(0xffffffffu, t2, off);
        if (gl == 0) {
            float iD = siD_[k];
            float term1 = iD * (x2 - 2.f * Crow[k] + smuSq_[k]);
            sll[warp][k] = sck_[k] - 0.5f * term1 + 0.5f * iD * iD * t2;
        }
    }
    __syncwarp();
    float llk = sll[warp][lane];
    float mx = llk;
    #pragma unroll
    for (int off = 16; off > 0; off >>= 1) mx = fmaxf(mx, __shfl_xor_sync(0xffffffffu, mx, off));
    float e = expf(llk - mx);
    float s = e;
    #pragma unroll
    for (int off = 16; off > 0; off >>= 1) s += __shfl_xor_sync(0xffffffffu, s, off);
    float r = e / s;
    float* Mrow = &gM2[n][0];
    Mrow[lane] = r;
    Mrow[544 + lane] = r * x2;
    Mrow[576 + lane] = 0.f;          // zero pad cols 576..639
    Mrow[608 + lane] = 0.f;
    #pragma unroll
    for (int it = 0; it < 16; ++it) {
        int j = it * 32 + lane;
        float rk = __shfl_sync(0xffffffffu, r, j >> 4);
        Mrow[32 + j] = rk * Crow[32 + j];
    }
}

// ---------------- column sums of M2 -> r_sum, G, rx2 ----------------
__global__ void __launch_bounds__(256) colsum_kernel() {
    int t = threadIdx.x;
    int col = blockIdx.x * 64 + (t & 63);
    int sub = t >> 6;
    int rowEnd = (blockIdx.y + 1) * 2048;
    float acc = 0.f;
    for (int row = blockIdx.y * 2048 + sub; row < rowEnd; row += 4)
        acc += gM2[row][col];
    __shared__ float sb[4][64];
    sb[sub][t & 63] = acc;
    __syncthreads();
    if (t < 64) {
        float s = sb[0][t] + sb[1][t] + sb[2][t] + sb[3][t];
        int c = blockIdx.x * 64 + t;
        if (c < 32)       atomicAdd(&grsum[c], s);
        else if (c < 544) atomicAdd(&gG[0][0] + (c - 32), s);
        else              atomicAdd(&grx2[c - 544], s);
    }
}

// ---------------- finalize mu + SiAi ----------------
__global__ void __launch_bounds__(256) finalize_kernel(float* __restrict__ outMu) {
    int idx = blockIdx.x * 256 + threadIdx.x;   // K*D = 32768
    int k = idx >> 10, d = idx & 1023;
    float rs = grsum[k];
    float inv = 1.f / rs;
    float mu = gSiAiRaw[d][k] * inv;
    gmu[k][d] = mu;
    outMu[idx] = mu;
    #pragma unroll
    for (int l = 0; l < 16; ++l)
        gSiAi2[k][d][l] = (gSiAiRaw[d][32 + k * 16 + l] - mu * gG[k][l]) * inv;
}

// ---------------- per-k M-step ----------------
__global__ void __launch_bounds__(256) mstep_kernel(const float* __restrict__ A,
                                                    float* __restrict__ outA,
                                                    float* __restrict__ outLogD,
                                                    float* __restrict__ outPI) {
    int k = blockIdx.x, t = threadIdx.x;
    int li = t >> 4, mi = t & 15;
    __shared__ float sS[16][16];
    __shared__ float sAs[16][16];
    float acc = 0.f;   // ATSiAi[li][mi]
    for (int d0 = 0; d0 < DD; d0 += 16) {
        __syncthreads();
        sAs[li][mi] = A[((size_t)k * DD + d0 + li) * LL + mi];
        sS [li][mi] = gSiAi2[k][d0 + li][mi];
        __syncthreads();
        #pragma unroll
        for (int dd = 0; dd < 16; ++dd) acc += sAs[dd][li] * sS[dd][mi];
    }
    __shared__ float sATS[16][16];
    __shared__ float siM[16][16];
    __syncthreads();
    sATS[li][mi] = acc;
    siM[li][mi] = gInvM[k][li][mi];
    __syncthreads();
    float Tv = 0.f;
    #pragma unroll
    for (int j = 0; j < 16; ++j) Tv += siM[li][j] * sATS[j][mi];
    __shared__ float aug[16][32];
    __shared__ float sfac[16];
    __shared__ int spiv;
    aug[li][mi]      = Tv + (li == mi ? gs2[k] : 0.f);
    aug[li][16 + mi] = (li == mi ? 1.f : 0.f);
    block_invert16(aug, nullptr, sfac, &spiv);
    __shared__ float sW2[16][16];
    sW2[li][mi] = aug[li][16 + mi];
    __syncthreads();
    float t1acc = 0.f;
    for (int d0 = 0; d0 < DD; d0 += 16) {
        __syncthreads();
        sS[li][mi] = gSiAi2[k][d0 + li][mi];
        __syncthreads();
        float an = 0.f, sim = 0.f;
        #pragma unroll
        for (int m = 0; m < 16; ++m) {
            float sv = sS[li][m];
            an  += sv * sW2[m][mi];
            sim += sv * siM[m][mi];
        }
        outA[((size_t)k * DD + d0 + li) * LL + mi] = an;
        t1acc += an * sim;
    }
    float msq = 0.f;
    for (int d = t; d < DD; d += 256) { float m = gmu[k][d]; msq += m * m; }
    __shared__ float sred[256];
    float t1   = block_reduce_sum(t1acc, sred);
    float msqs = block_reduce_sum(msq, sred);
    __shared__ float sld;
    if (t == 0) {
        float rs = grsum[k];
        float traceS = (grx2[k] - rs * msqs) / rs;
        float sig2 = (traceS - t1) / (float)DD;
        sld = logf(sig2);
        float tot = 0.f;
        for (int j = 0; j < KK; ++j) tot += grsum[j];
        outPI[k] = logf(grsum[k] / tot);
    }
    __syncthreads();
    float ldv = sld;
    for (int d = t; d < DD; d += 256) outLogD[k * DD + d] = ldv;
}

// ---------------- launch ----------------
extern "C" void kernel_launch(void* const* d_in, const int* in_sizes, int n_in,
                              void* d_out, int out_size) {
    const float* x   = (const float*)d_in[0];
    const float* MU  = (const float*)d_in[1];
    const float* A   = (const float*)d_in[2];
    const float* lD  = (const float*)d_in[3];
    const float* PIl = (const float*)d_in[4];
    float* out = (float*)d_out;
    float* outMu   = out;                       // [32,1024]
    float* outA    = out + KK * DD;             // [32,1024,16]
    float* outLogD = out + KK * DD + KK * DD * LL;
    float* outPI   = out + KK * DD + KK * DD * LL + KK * DD;

    zero_kernel<<<1024, 256>>>();
    setup_kernel<<<KK, 256>>>(MU, A, lD, PIl);
    x2_kernel<<<NN / 8, 256>>>(x);
    gemm_b2<<<dim3(NN / 128, WPAD / 128), 256>>>(x);
    estep_epilogue<<<NN / 8, 256>>>();
    colsum_kernel<<<dim3(576 / 64, 8), 256>>>();
    gemm_d<<<dim3(DD / 128, M2W / 128, 8), 256>>>(x);
    finalize_kernel<<<(KK * DD) / 256, 256>>>(outMu);
    mstep_kernel<<<KK, 256>>>(A, outA, outLogD, outPI);
}

// round 4
// speedup vs baseline: 2.0298x; 1.6354x over previous
#include <cuda_runtime.h>
#include <cuda_bf16.h>
#include <math.h>
#include <stdint.h>

// Problem dims (fixed by setup_inputs)
#define NN 16384
#define DD 1024
#define KK 32
#define LL 16
#define WPAD 640
#define M2W 640
#define LOG2PI_F 1.8378770664093453f

// ---------------- device scratch ----------------
__device__ __align__(16) __nv_bfloat16 gXhi [NN][DD];
__device__ __align__(16) __nv_bfloat16 gXlo [NN][DD];
__device__ __align__(16) __nv_bfloat16 gXThi[DD][NN];
__device__ __align__(16) __nv_bfloat16 gXTlo[DD][NN];
__device__ __align__(16) __nv_bfloat16 gWThi[WPAD][DD];
__device__ __align__(16) __nv_bfloat16 gWTlo[WPAD][DD];
__device__ __align__(16) __nv_bfloat16 gM2Thi[M2W][NN];
__device__ __align__(16) __nv_bfloat16 gM2Tlo[M2W][NN];
__device__ float gC [NN][WPAD];        // x @ [MU|A]
__device__ float gM2[NN][M2W];         // [r | r*q | r*x2 | pad]
__device__ float gX2[NN];
__device__ float gSiAiRaw[DD][M2W];    // x^T @ M2
__device__ float gSiAi2[KK][DD][LL];
__device__ float gmu[KK][DD];
__device__ float giL  [KK][LL][LL];
__device__ float gInvM[KK][LL][LL];
__device__ float gbmu [KK][LL];
__device__ float gG   [KK][LL];
__device__ float gmuSq[KK];
__device__ float giD [KK];
__device__ float gck[KK];
__device__ float gs2[KK];
__device__ float grsum[KK];
__device__ float grx2[KK];

// ---------------- helpers ----------------
__device__ __forceinline__ uint32_t s2u(const void* p) {
    uint32_t a;
    asm("{ .reg .u64 t; cvta.to.shared.u64 t, %1; cvt.u32.u64 %0, t; }" : "=r"(a) : "l"(p));
    return a;
}

__device__ __forceinline__ void ldm4(uint32_t* r, uint32_t addr) {
    asm volatile("ldmatrix.sync.aligned.m8n8.x4.shared.b16 {%0,%1,%2,%3}, [%4];"
                 : "=r"(r[0]), "=r"(r[1]), "=r"(r[2]), "=r"(r[3]) : "r"(addr));
}

__device__ __forceinline__ void mma16816(float* c, const uint32_t* a, uint32_t b0, uint32_t b1) {
    asm volatile(
        "mma.sync.aligned.m16n8k16.row.col.f32.bf16.bf16.f32 "
        "{%0,%1,%2,%3}, {%4,%5,%6,%7}, {%8,%9}, {%0,%1,%2,%3};"
        : "+f"(c[0]), "+f"(c[1]), "+f"(c[2]), "+f"(c[3])
        : "r"(a[0]), "r"(a[1]), "r"(a[2]), "r"(a[3]), "r"(b0), "r"(b1));
}

__device__ __forceinline__ float block_reduce_sum(float v, float* sbuf) {
    int t = threadIdx.x;
    sbuf[t] = v; __syncthreads();
    for (int s = 128; s > 0; s >>= 1) {
        if (t < s) sbuf[t] += sbuf[t + s];
        __syncthreads();
    }
    float r = sbuf[0];
    __syncthreads();
    return r;
}

__device__ void block_invert16(float aug[16][32], float* slogdet, float* sfac, int* spiv) {
    int t = threadIdx.x;
    int r = t >> 4, c = t & 15;
    for (int p = 0; p < 16; ++p) {
        __syncthreads();
        if (t == 0) {
            int best = p; float bv = fabsf(aug[p][p]);
            for (int rr = p + 1; rr < 16; ++rr) {
                float v = fabsf(aug[rr][p]);
                if (v > bv) { bv = v; best = rr; }
            }
            *spiv = best;
            if (slogdet) *slogdet += logf(fmaxf(bv, 1e-30f));
        }
        __syncthreads();
        int pr = *spiv;
        if (pr != p && t < 32) { float tmp = aug[p][t]; aug[p][t] = aug[pr][t]; aug[pr][t] = tmp; }
        __syncthreads();
        if (t < 32) {
            float val = aug[p][t];
            float pv  = aug[p][p];
            __syncwarp();
            aug[p][t] = val / pv;
        }
        __syncthreads();
        if (c == 0) sfac[r] = aug[r][p];
        __syncthreads();
        if (r != p) {
            float f = sfac[r];
            aug[r][c]      -= f * aug[p][c];
            aug[r][c + 16] -= f * aug[p][c + 16];
        }
    }
    __syncthreads();
}

// ---------------- kernel 0: zero scratch ----------------
__global__ void zero_kernel() {
    size_t i0 = (size_t)blockIdx.x * blockDim.x + threadIdx.x;
    size_t str = (size_t)gridDim.x * blockDim.x;
    float* p;
    p = &gSiAiRaw[0][0]; for (size_t i = i0; i < (size_t)DD * M2W; i += str) p[i] = 0.f;
    __nv_bfloat16 z = __float2bfloat16(0.f);
    for (size_t i = i0; i < (size_t)96 * DD; i += str) {
        (&gWThi[544][0])[i] = z;
        (&gWTlo[544][0])[i] = z;
    }
    if (i0 < KK) { grsum[i0] = 0.f; grx2[i0] = 0.f; }
    p = &gG[0][0]; if (i0 < KK * LL) p[i0] = 0.f;
}

// ---------------- split x (straight, hi/lo) ----------------
__global__ void __launch_bounds__(256) splitx_kernel(const float* __restrict__ x) {
    size_t i = (size_t)blockIdx.x * 256 + threadIdx.x;   // one float4 each
    float4 v = ((const float4*)x)[i];
    __nv_bfloat16 h0 = __float2bfloat16(v.x), h1 = __float2bfloat16(v.y);
    __nv_bfloat16 h2 = __float2bfloat16(v.z), h3 = __float2bfloat16(v.w);
    ushort4 ph, pl;
    ph.x = __bfloat16_as_ushort(h0); ph.y = __bfloat16_as_ushort(h1);
    ph.z = __bfloat16_as_ushort(h2); ph.w = __bfloat16_as_ushort(h3);
    pl.x = __bfloat16_as_ushort(__float2bfloat16(v.x - __bfloat162float(h0)));
    pl.y = __bfloat16_as_ushort(__float2bfloat16(v.y - __bfloat162float(h1)));
    pl.z = __bfloat16_as_ushort(__float2bfloat16(v.z - __bfloat162float(h2)));
    pl.w = __bfloat16_as_ushort(__float2bfloat16(v.w - __bfloat162float(h3)));
    ((ushort4*)&gXhi[0][0])[i] = ph;
    ((ushort4*)&gXlo[0][0])[i] = pl;
}

// ---------------- transpose + split: src[H][W] f32 -> dhi/dlo[W][H] bf16 ----------------
__global__ void __launch_bounds__(256) tsplit_kernel(const float* __restrict__ src, int W, int H,
                                                     __nv_bfloat16* __restrict__ dhi,
                                                     __nv_bfloat16* __restrict__ dlo) {
    __shared__ float tile[32][33];
    int tx = threadIdx.x & 31, ty = threadIdx.x >> 5;
    int c0 = blockIdx.x * 32;
    int r0 = blockIdx.y * 32;
    #pragma unroll
    for (int j = 0; j < 32; j += 8)
        tile[ty + j][tx] = src[(size_t)(r0 + ty + j) * W + c0 + tx];
    __syncthreads();
    #pragma unroll
    for (int j = 0; j < 32; j += 8) {
        int w = c0 + ty + j;
        int h = r0 + tx;
        float v = tile[tx][ty + j];
        __nv_bfloat16 hi = __float2bfloat16(v);
        dhi[(size_t)w * H + h] = hi;
        dlo[(size_t)w * H + h] = __float2bfloat16(v - __bfloat162float(hi));
    }
}

// ---------------- x2 kernel ----------------
__global__ void __launch_bounds__(256) x2_kernel(const float* __restrict__ x) {
    int warp = threadIdx.x >> 5, lane = threadIdx.x & 31;
    int n = blockIdx.x * 8 + warp;
    const float4* xr = (const float4*)(x + (size_t)n * DD);
    float s = 0.f;
    #pragma unroll
    for (int c = lane; c < 256; c += 32) {
        float4 v = xr[c];
        s += v.x * v.x + v.y * v.y + v.z * v.z + v.w * v.w;
    }
    #pragma unroll
    for (int off = 16; off > 0; off >>= 1) s += __shfl_xor_sync(0xffffffffu, s, off);
    if (lane == 0) gX2[n] = s;
}

// ---------------- per-k setup (isotropic iD); also builds WT hi/lo ----------------
__global__ void setup_kernel(const float* __restrict__ MU, const float* __restrict__ A,
                             const float* __restrict__ log_D, const float* __restrict__ PI_logits) {
    int k = blockIdx.x, t = threadIdx.x;
    __shared__ float sred[256];
    __shared__ float sPIk;
    if (t == 0) {
        float mx = -1e30f;
        for (int j = 0; j < KK; ++j) mx = fmaxf(mx, PI_logits[j]);
        float s = 0.f;
        for (int j = 0; j < KK; ++j) s += expf(PI_logits[j] - mx);
        sPIk = expf(PI_logits[k] - mx) / s;
    }
    float ld0 = log_D[(size_t)k * DD];
    float iD = expf(-ld0);
    float s2 = expf(ld0);
    float muSqAcc = 0.f;
    for (int d = t; d < DD; d += 256) {
        float mu = MU[(size_t)k * DD + d];
        __nv_bfloat16 h = __float2bfloat16(mu);
        gWThi[k][d] = h;
        gWTlo[k][d] = __float2bfloat16(mu - __bfloat162float(h));
        muSqAcc += mu * mu;
    }
    float bmuAcc = 0.f;
    {
        int l = t & 15;
        for (int d = t >> 4; d < DD; d += 16) {
            float a = A[((size_t)k * DD + d) * LL + l];
            __nv_bfloat16 h = __float2bfloat16(a);
            gWThi[32 + k * 16 + l][d] = h;
            gWTlo[32 + k * 16 + l][d] = __float2bfloat16(a - __bfloat162float(h));
            bmuAcc += MU[(size_t)k * DD + d] * a;
        }
    }
    int li = t >> 4, mi = t & 15;
    float ATAacc = 0.f;
    __shared__ float sA[16][16];
    for (int d0 = 0; d0 < DD; d0 += 16) {
        __syncthreads();
        sA[li][mi] = A[((size_t)k * DD + d0 + li) * LL + mi];
        __syncthreads();
        #pragma unroll
        for (int dd = 0; dd < 16; ++dd) ATAacc += sA[dd][li] * sA[dd][mi];
    }
    float muSqK = block_reduce_sum(muSqAcc, sred);
    __shared__ float sbm[16][17];
    sbm[t & 15][t >> 4] = bmuAcc;
    __syncthreads();
    if (t < 16) {
        float s = 0.f;
        for (int g = 0; g < 16; ++g) s += sbm[t][g];
        gbmu[k][t] = s;
    }
    __shared__ float aug[16][32];
    __shared__ float sfac[16];
    __shared__ int spiv;
    __shared__ float slogdet;
    if (t == 0) slogdet = 0.f;
    __syncthreads();
    aug[li][mi]      = iD * ATAacc + (li == mi ? 1.f : 0.f);
    aug[li][16 + mi] = (li == mi ? 1.f : 0.f);
    block_invert16(aug, &slogdet, sfac, &spiv);
    giL[k][li][mi] = aug[li][16 + mi];
    float logdetL = slogdet;
    __syncthreads();
    aug[li][mi]      = ATAacc + (li == mi ? s2 : 0.f);
    aug[li][16 + mi] = (li == mi ? 1.f : 0.f);
    block_invert16(aug, nullptr, sfac, &spiv);
    gInvM[k][li][mi] = aug[li][16 + mi];
    if (t == 0) {
        gmuSq[k] = muSqK;
        giD[k] = iD;
        gs2[k] = s2;
        gck[k] = sPIk - 0.5f * ((float)DD * LOG2PI_F + logdetL + (float)DD * ld0);
    }
}

// ---------------- mma.sync bf16x3 GEMM ----------------
// C[m0+128, n0+64] (+)= A·B^T, A:[M][lda], B:[N][ldb] both K-major bf16 (hi/lo).
// CTA 256 thr = 8 warps (4m x 2n), warp tile 32x32, K-chunk 32, double-buffered.
#define SROW 40                     // padded row length (bf16 elems)
#define OFF_AHI 0
#define OFF_ALO (128 * SROW * 2)
#define OFF_BHI (2 * 128 * SROW * 2)
#define OFF_BLO (2 * 128 * SROW * 2 + 64 * SROW * 2)
#define BUFSZ   (2 * 128 * SROW * 2 + 2 * 64 * SROW * 2)   // 30720

template<bool ATOMIC>
__global__ void __launch_bounds__(256, 2) mma_gemm_kernel(
    const __nv_bfloat16* __restrict__ Ahi, const __nv_bfloat16* __restrict__ Alo, int lda,
    const __nv_bfloat16* __restrict__ Bhi, const __nv_bfloat16* __restrict__ Blo, int ldb,
    float* __restrict__ C, int ldc, int kLen)
{
    extern __shared__ __align__(128) char ds[];
    const uint32_t sbase = s2u(ds);
    const int t = threadIdx.x, lane = t & 31, w = t >> 5;
    const int wm = w & 3, wn = w >> 2;
    const int m0 = blockIdx.x * 128;
    const int n0 = blockIdx.y * 64;
    const int kBeg = blockIdx.z * kLen;
    const int nCh = kLen >> 5;

    // LDG/STS geometry (per chunk): A 512 uint4 slots, B 256 each
    const int arow0 = t >> 2, aq = (t & 3) * 8;       // A slot t  (rows 0..63)
    const int arow1 = arow0 + 64;                     // A slot t+256
    const int brow = t >> 2;                          // B slot t (rows 0..63)
    const size_t gA0 = (size_t)(m0 + arow0) * lda + kBeg + aq;
    const size_t gA1 = (size_t)(m0 + arow1) * lda + kBeg + aq;
    const size_t gB0 = (size_t)(n0 + brow) * ldb + kBeg + aq;
    const int sA0 = (arow0 * SROW + aq) * 2;
    const int sA1 = (arow1 * SROW + aq) * 2;
    const int sB0 = (brow * SROW + aq) * 2;

    // ldmatrix per-lane offsets (elements)
    const int aoff = (wm * 32 + (lane & 15)) * SROW + ((lane >> 4) << 3);
    const int boff = (wn * 32 + (lane & 15)) * SROW + ((lane >> 4) << 3);

    float acc[2][4][4] = {};
    uint4 rAh0, rAh1, rAl0, rAl1, rBh, rBl;

    // preload chunk 0
    rAh0 = *(const uint4*)(Ahi + gA0); rAh1 = *(const uint4*)(Ahi + gA1);
    rAl0 = *(const uint4*)(Alo + gA0); rAl1 = *(const uint4*)(Alo + gA1);
    rBh  = *(const uint4*)(Bhi + gB0); rBl  = *(const uint4*)(Blo + gB0);
    *(uint4*)(ds + OFF_AHI + sA0) = rAh0; *(uint4*)(ds + OFF_AHI + sA1) = rAh1;
    *(uint4*)(ds + OFF_ALO + sA0) = rAl0; *(uint4*)(ds + OFF_ALO + sA1) = rAl1;
    *(uint4*)(ds + OFF_BHI + sB0) = rBh;  *(uint4*)(ds + OFF_BLO + sB0) = rBl;
    __syncthreads();

    int buf = 0;
    for (int ch = 0; ch < nCh; ++ch) {
        if (ch + 1 < nCh) {
            int kk = (ch + 1) * 32;
            rAh0 = *(const uint4*)(Ahi + gA0 + kk); rAh1 = *(const uint4*)(Ahi + gA1 + kk);
            rAl0 = *(const uint4*)(Alo + gA0 + kk); rAl1 = *(const uint4*)(Alo + gA1 + kk);
            rBh  = *(const uint4*)(Bhi + gB0 + kk); rBl  = *(const uint4*)(Blo + gB0 + kk);
        }
        uint32_t bA_h = sbase + buf * BUFSZ + OFF_AHI;
        uint32_t bA_l = sbase + buf * BUFSZ + OFF_ALO;
        uint32_t bB_h = sbase + buf * BUFSZ + OFF_BHI;
        uint32_t bB_l = sbase + buf * BUFSZ + OFF_BLO;
        #pragma unroll
        for (int k0 = 0; k0 < 32; k0 += 16) {
            uint32_t ah[2][4], al[2][4], bh[2][4], bl[2][4];
            #pragma unroll
            for (int mf = 0; mf < 2; ++mf) {
                ldm4(ah[mf], bA_h + (aoff + mf * 16 * SROW + k0) * 2);
                ldm4(al[mf], bA_l + (aoff + mf * 16 * SROW + k0) * 2);
            }
            #pragma unroll
            for (int p = 0; p < 2; ++p) {
                ldm4(bh[p], bB_h + (boff + p * 16 * SROW + k0) * 2);
                ldm4(bl[p], bB_l + (boff + p * 16 * SROW + k0) * 2);
            }
            #pragma unroll
            for (int mf = 0; mf < 2; ++mf)
                #pragma unroll
                for (int nf = 0; nf < 4; ++nf) {
                    int p = nf >> 1, o = nf & 1;
                    mma16816(acc[mf][nf], ah[mf], bh[p][o], bh[p][2 + o]);
                    mma16816(acc[mf][nf], ah[mf], bl[p][o], bl[p][2 + o]);
                    mma16816(acc[mf][nf], al[mf], bh[p][o], bh[p][2 + o]);
                }
        }
        if (ch + 1 < nCh) {
            char* dsn = ds + (buf ^ 1) * BUFSZ;
            *(uint4*)(dsn + OFF_AHI + sA0) = rAh0; *(uint4*)(dsn + OFF_AHI + sA1) = rAh1;
            *(uint4*)(dsn + OFF_ALO + sA0) = rAl0; *(uint4*)(dsn + OFF_ALO + sA1) = rAl1;
            *(uint4*)(dsn + OFF_BHI + sB0) = rBh;  *(uint4*)(dsn + OFF_BLO + sB0) = rBl;
            __syncthreads();
            buf ^= 1;
        }
    }

    // epilogue
    const int gid = lane >> 2, tid = lane & 3;
    #pragma unroll
    for (int mf = 0; mf < 2; ++mf) {
        #pragma unroll
        for (int nf = 0; nf < 4; ++nf) {
            int row = m0 + wm * 32 + mf * 16 + gid;
            int col = n0 + wn * 32 + nf * 8 + tid * 2;
            float* c0 = C + (size_t)row * ldc + col;
            float* c1 = C + (size_t)(row + 8) * ldc + col;
            if (ATOMIC) {
                atomicAdd(c0,     acc[mf][nf][0]);
                atomicAdd(c0 + 1, acc[mf][nf][1]);
                atomicAdd(c1,     acc[mf][nf][2]);
                atomicAdd(c1 + 1, acc[mf][nf][3]);
            } else {
                *(float2*)c0 = make_float2(acc[mf][nf][0], acc[mf][nf][1]);
                *(float2*)c1 = make_float2(acc[mf][nf][2], acc[mf][nf][3]);
            }
        }
    }
}

// ---------------- E-step epilogue: logits -> r, build M2 ----------------
__global__ void __launch_bounds__(256) estep_epilogue() {
    __shared__ float siLs[KK * 272];
    __shared__ float sbmu_[KK][LL];
    __shared__ float smuSq_[KK];
    __shared__ float siD_[KK];
    __shared__ float sck_[KK];
    __shared__ float sll[8][32];
    int t = threadIdx.x;
    for (int idx = t; idx < KK * 256; idx += 256) {
        int kk = idx >> 8, rem = idx & 255;
        siLs[kk * 272 + (rem >> 4) * 17 + (rem & 15)] = (&giL[0][0][0])[idx];
    }
    for (int idx = t; idx < KK * LL; idx += 256) (&sbmu_[0][0])[idx] = (&gbmu[0][0])[idx];
    if (t < KK) { smuSq_[t] = gmuSq[t]; sck_[t] = gck[t]; siD_[t] = giD[t]; }
    __syncthreads();

    int warp = t >> 5, lane = t & 31;
    int n = blockIdx.x * 8 + warp;
    const float* Crow = &gC[n][0];
    float x2 = gX2[n];
    #pragma unroll 1
    for (int it = 0; it < 16; ++it) {
        int k = it * 2 + (lane >> 4);
        int gl = lane & 15;
        float yv = Crow[32 + k * 16 + gl] - sbmu_[k][gl];
        float z = 0.f;
        const float* ilr = &siLs[k * 272 + gl * 17];
        #pragma unroll
        for (int m = 0; m < 16; ++m) {
            float ym = __shfl_sync(0xffffffffu, yv, (lane & 16) | m);
            z += ilr[m] * ym;
        }
        float t2 = z * yv;
        #pragma unroll
        for (int off = 8; off > 0; off >>= 1) t2 += __shfl_xor_sync(0xffffffffu, t2, off);
        if (gl == 0) {
            float iD = siD_[k];
            float term1 = iD * (x2 - 2.f * Crow[k] + smuSq_[k]);
            sll[warp][k] = sck_[k] - 0.5f * term1 + 0.5f * iD * iD * t2;
        }
    }
    __syncwarp();
    float llk = sll[warp][lane];
    float mx = llk;
    #pragma unroll
    for (int off = 16; off > 0; off >>= 1) mx = fmaxf(mx, __shfl_xor_sync(0xffffffffu, mx, off));
    float e = expf(llk - mx);
    float s = e;
    #pragma unroll
    for (int off = 16; off > 0; off >>= 1) s += __shfl_xor_sync(0xffffffffu, s, off);
    float r = e / s;
    float* Mrow = &gM2[n][0];
    Mrow[lane] = r;
    Mrow[544 + lane] = r * x2;
    Mrow[576 + lane] = 0.f;
    Mrow[608 + lane] = 0.f;
    #pragma unroll
    for (int it = 0; it < 16; ++it) {
        int j = it * 32 + lane;
        float rk = __shfl_sync(0xffffffffu, r, j >> 4);
        Mrow[32 + j] = rk * Crow[32 + j];
    }
}

// ---------------- column sums of M2 ----------------
__global__ void __launch_bounds__(256) colsum_kernel() {
    int t = threadIdx.x;
    int col = blockIdx.x * 64 + (t & 63);
    int sub = t >> 6;
    int rowEnd = (blockIdx.y + 1) * 2048;
    float acc = 0.f;
    for (int row = blockIdx.y * 2048 + sub; row < rowEnd; row += 4)
        acc += gM2[row][col];
    __shared__ float sb[4][64];
    sb[sub][t & 63] = acc;
    __syncthreads();
    if (t < 64) {
        float s = sb[0][t] + sb[1][t] + sb[2][t] + sb[3][t];
        int c = blockIdx.x * 64 + t;
        if (c < 32)       atomicAdd(&grsum[c], s);
        else if (c < 544) atomicAdd(&gG[0][0] + (c - 32), s);
        else              atomicAdd(&grx2[c - 544], s);
    }
}

// ---------------- finalize mu + SiAi ----------------
__global__ void __launch_bounds__(256) finalize_kernel(float* __restrict__ outMu) {
    int idx = blockIdx.x * 256 + threadIdx.x;
    int k = idx >> 10, d = idx & 1023;
    float rs = grsum[k];
    float inv = 1.f / rs;
    float mu = gSiAiRaw[d][k] * inv;
    gmu[k][d] = mu;
    outMu[idx] = mu;
    #pragma unroll
    for (int l = 0; l < 16; ++l)
        gSiAi2[k][d][l] = (gSiAiRaw[d][32 + k * 16 + l] - mu * gG[k][l]) * inv;
}

// ---------------- per-k M-step ----------------
__global__ void __launch_bounds__(256) mstep_kernel(const float* __restrict__ A,
                                                    float* __restrict__ outA,
                                                    float* __restrict__ outLogD,
                                                    float* __restrict__ outPI) {
    int k = blockIdx.x, t = threadIdx.x;
    int li = t >> 4, mi = t & 15;
    __shared__ float sS[16][16];
    __shared__ float sAs[16][16];
    float acc = 0.f;
    for (int d0 = 0; d0 < DD; d0 += 16) {
        __syncthreads();
        sAs[li][mi] = A[((size_t)k * DD + d0 + li) * LL + mi];
        sS [li][mi] = gSiAi2[k][d0 + li][mi];
        __syncthreads();
        #pragma unroll
        for (int dd = 0; dd < 16; ++dd) acc += sAs[dd][li] * sS[dd][mi];
    }
    __shared__ float sATS[16][16];
    __shared__ float siM[16][16];
    __syncthreads();
    sATS[li][mi] = acc;
    siM[li][mi] = gInvM[k][li][mi];
    __syncthreads();
    float Tv = 0.f;
    #pragma unroll
    for (int j = 0; j < 16; ++j) Tv += siM[li][j] * sATS[j][mi];
    __shared__ float aug[16][32];
    __shared__ float sfac[16];
    __shared__ int spiv;
    aug[li][mi]      = Tv + (li == mi ? gs2[k] : 0.f);
    aug[li][16 + mi] = (li == mi ? 1.f : 0.f);
    block_invert16(aug, nullptr, sfac, &spiv);
    __shared__ float sW2[16][16];
    sW2[li][mi] = aug[li][16 + mi];
    __syncthreads();
    float t1acc = 0.f;
    for (int d0 = 0; d0 < DD; d0 += 16) {
        __syncthreads();
        sS[li][mi] = gSiAi2[k][d0 + li][mi];
        __syncthreads();
        float an = 0.f, sim = 0.f;
        #pragma unroll
        for (int m = 0; m < 16; ++m) {
            float sv = sS[li][m];
            an  += sv * sW2[m][mi];
            sim += sv * siM[m][mi];
        }
        outA[((size_t)k * DD + d0 + li) * LL + mi] = an;
        t1acc += an * sim;
    }
    float msq = 0.f;
    for (int d = t; d < DD; d += 256) { float m = gmu[k][d]; msq += m * m; }
    __shared__ float sred[256];
    float t1   = block_reduce_sum(t1acc, sred);
    float msqs = block_reduce_sum(msq, sred);
    __shared__ float sld;
    if (t == 0) {
        float rs = grsum[k];
        float traceS = (grx2[k] - rs * msqs) / rs;
        float sig2 = (traceS - t1) / (float)DD;
        sld = logf(sig2);
        float tot = 0.f;
        for (int j = 0; j < KK; ++j) tot += grsum[j];
        outPI[k] = logf(grsum[k] / tot);
    }
    __syncthreads();
    float ldv = sld;
    for (int d = t; d < DD; d += 256) outLogD[k * DD + d] = ldv;
}

// ---------------- launch ----------------
extern "C" void kernel_launch(void* const* d_in, const int* in_sizes, int n_in,
                              void* d_out, int out_size) {
    const float* x   = (const float*)d_in[0];
    const float* MU  = (const float*)d_in[1];
    const float* A   = (const float*)d_in[2];
    const float* lD  = (const float*)d_in[3];
    const float* PIl = (const float*)d_in[4];
    float* out = (float*)d_out;
    float* outMu   = out;
    float* outA    = out + KK * DD;
    float* outLogD = out + KK * DD + KK * DD * LL;
    float* outPI   = out + KK * DD + KK * DD * LL + KK * DD;

    const int DSMEM = 2 * BUFSZ;   // 61440
    cudaFuncSetAttribute(mma_gemm_kernel<false>, cudaFuncAttributeMaxDynamicSharedMemorySize, DSMEM);
    cudaFuncSetAttribute(mma_gemm_kernel<true>,  cudaFuncAttributeMaxDynamicSharedMemorySize, DSMEM);

    __nv_bfloat16 *pXhi, *pXlo, *pXThi, *pXTlo, *pWThi, *pWTlo, *pM2Thi, *pM2Tlo;
    float *pM2, *pC, *pSiAi;
    cudaGetSymbolAddress((void**)&pXhi,   gXhi);
    cudaGetSymbolAddress((void**)&pXlo,   gXlo);
    cudaGetSymbolAddress((void**)&pXThi,  gXThi);
    cudaGetSymbolAddress((void**)&pXTlo,  gXTlo);
    cudaGetSymbolAddress((void**)&pWThi,  gWThi);
    cudaGetSymbolAddress((void**)&pWTlo,  gWTlo);
    cudaGetSymbolAddress((void**)&pM2Thi, gM2Thi);
    cudaGetSymbolAddress((void**)&pM2Tlo, gM2Tlo);
    cudaGetSymbolAddress((void**)&pM2,    gM2);
    cudaGetSymbolAddress((void**)&pC,     gC);
    cudaGetSymbolAddress((void**)&pSiAi,  gSiAiRaw);

    zero_kernel<<<1024, 256>>>();
    splitx_kernel<<<(NN * DD / 4) / 256, 256>>>(x);
    tsplit_kernel<<<dim3(DD / 32, NN / 32), 256>>>(x, DD, NN, pXThi, pXTlo);
    x2_kernel<<<NN / 8, 256>>>(x);
    setup_kernel<<<KK, 256>>>(MU, A, lD, PIl);
    // GEMM1: C[16384,640] = X @ W^T (B rows = WT)
    mma_gemm_kernel<false><<<dim3(NN / 128, WPAD / 64, 1), 256, DSMEM>>>(
        pXhi, pXlo, DD, pWThi, pWTlo, DD, pC, WPAD, DD);
    estep_epilogue<<<NN / 8, 256>>>();
    colsum_kernel<<<dim3(576 / 64, 8), 256>>>();
    tsplit_kernel<<<dim3(M2W / 32, NN / 32), 256>>>(pM2, M2W, NN, pM2Thi, pM2Tlo);
    // GEMM_d: SiAi[1024,640] = XT @ M2T^T, k-split 4 with atomic accumulation
    mma_gemm_kernel<true><<<dim3(DD / 128, M2W / 64, 4), 256, DSMEM>>>(
        pXThi, pXTlo, NN, pM2Thi, pM2Tlo, NN, pSiAi, M2W, NN / 4);
    finalize_kernel<<<(KK * DD) / 256, 256>>>(outMu);
    mstep_kernel<<<KK, 256>>>(A, outA, outLogD, outPI);
}

// round 5
// speedup vs baseline: 2.1144x; 1.0417x over previous
#include <cuda_runtime.h>
#include <cuda_bf16.h>
#include <math.h>
#include <stdint.h>

#define NN 16384
#define DD 1024
#define KK 32
#define LL 16
#define WPAD 640
#define M2W 640
#define LOG2PI_F 1.8378770664093453f

// ---------------- device scratch ----------------
__device__ __align__(16) __nv_bfloat16 gXhi [NN][DD];
__device__ __align__(16) __nv_bfloat16 gXlo [NN][DD];
__device__ __align__(16) __nv_bfloat16 gXThi[DD][NN];
__device__ __align__(16) __nv_bfloat16 gXTlo[DD][NN];
__device__ __align__(16) __nv_bfloat16 gWThi[WPAD][DD];
__device__ __align__(16) __nv_bfloat16 gWTlo[WPAD][DD];
__device__ __align__(16) __nv_bfloat16 gM2Thi[M2W][NN];
__device__ __align__(16) __nv_bfloat16 gM2Tlo[M2W][NN];
__device__ float gC [NN][WPAD];
__device__ float gM2[NN][M2W];
__device__ float gX2[NN];
__device__ float gSiAiP[DD][8][M2W];   // 8 k-split slabs, interleaved per d
__device__ float gSiAi2[KK][DD][LL];
__device__ float gmu[KK][DD];
__device__ float giL  [KK][LL][LL];
__device__ float gInvM[KK][LL][LL];
__device__ float gbmu [KK][LL];
__device__ float gG   [KK][LL];
__device__ float gmuSq[KK];
__device__ float giD [KK];
__device__ float gck[KK];
__device__ float gs2[KK];
__device__ float grsum[KK];
__device__ float grx2[KK];

// ---------------- helpers ----------------
__device__ __forceinline__ uint32_t s2u(const void* p) {
    uint32_t a;
    asm("{ .reg .u64 t; cvta.to.shared.u64 t, %1; cvt.u32.u64 %0, t; }" : "=r"(a) : "l"(p));
    return a;
}
__device__ __forceinline__ void ldm4(uint32_t* r, uint32_t addr) {
    asm volatile("ldmatrix.sync.aligned.m8n8.x4.shared.b16 {%0,%1,%2,%3}, [%4];"
                 : "=r"(r[0]), "=r"(r[1]), "=r"(r[2]), "=r"(r[3]) : "r"(addr));
}
__device__ __forceinline__ void mma16816(float* c, const uint32_t* a, uint32_t b0, uint32_t b1) {
    asm volatile(
        "mma.sync.aligned.m16n8k16.row.col.f32.bf16.bf16.f32 "
        "{%0,%1,%2,%3}, {%4,%5,%6,%7}, {%8,%9}, {%0,%1,%2,%3};"
        : "+f"(c[0]), "+f"(c[1]), "+f"(c[2]), "+f"(c[3])
        : "r"(a[0]), "r"(a[1]), "r"(a[2]), "r"(a[3]), "r"(b0), "r"(b1));
}
__device__ __forceinline__ float block_reduce_sum(float v, float* sbuf) {
    int t = threadIdx.x;
    sbuf[t] = v; __syncthreads();
    for (int s = 128; s > 0; s >>= 1) {
        if (t < s) sbuf[t] += sbuf[t + s];
        __syncthreads();
    }
    float r = sbuf[0];
    __syncthreads();
    return r;
}
__device__ void block_invert16(float aug[16][32], float* slogdet, float* sfac, int* spiv) {
    int t = threadIdx.x;
    int r = t >> 4, c = t & 15;
    for (int p = 0; p < 16; ++p) {
        __syncthreads();
        if (t == 0) {
            int best = p; float bv = fabsf(aug[p][p]);
            for (int rr = p + 1; rr < 16; ++rr) {
                float v = fabsf(aug[rr][p]);
                if (v > bv) { bv = v; best = rr; }
            }
            *spiv = best;
            if (slogdet) *slogdet += logf(fmaxf(bv, 1e-30f));
        }
        __syncthreads();
        int pr = *spiv;
        if (pr != p && t < 32) { float tmp = aug[p][t]; aug[p][t] = aug[pr][t]; aug[pr][t] = tmp; }
        __syncthreads();
        if (t < 32) {
            float val = aug[p][t];
            float pv  = aug[p][p];
            __syncwarp();
            aug[p][t] = val / pv;
        }
        __syncthreads();
        if (c == 0) sfac[r] = aug[r][p];
        __syncthreads();
        if (r != p) {
            float f = sfac[r];
            aug[r][c]      -= f * aug[p][c];
            aug[r][c + 16] -= f * aug[p][c + 16];
        }
    }
    __syncthreads();
}

// ---------------- kernel 0: zero scratch ----------------
__global__ void zero_kernel() {
    size_t i0 = (size_t)blockIdx.x * blockDim.x + threadIdx.x;
    size_t str = (size_t)gridDim.x * blockDim.x;
    __nv_bfloat16 z = __float2bfloat16(0.f);
    for (size_t i = i0; i < (size_t)96 * DD; i += str) {
        (&gWThi[544][0])[i] = z;
        (&gWTlo[544][0])[i] = z;
    }
    for (size_t i = i0; i < (size_t)NN; i += str) gX2[i] = 0.f;
    if (i0 < KK) { grsum[i0] = 0.f; grx2[i0] = 0.f; }
    float* p = &gG[0][0]; if (i0 < KK * LL) p[i0] = 0.f;
}

// ---------------- fused x preprocessing ----------------
// 32x32 tiles: straight split, transposed split, x2 partial sums.
__global__ void __launch_bounds__(256) xprep_kernel(const float* __restrict__ x) {
    __shared__ float tile[32][33];
    int t = threadIdx.x;
    int tx8 = t & 7, ty = t >> 3;           // 8 col-quads x 32 rows
    int c0 = blockIdx.x * 32, r0 = blockIdx.y * 32;
    float4 v = *(const float4*)(x + (size_t)(r0 + ty) * DD + c0 + tx8 * 4);
    // straight hi/lo
    __nv_bfloat16 h0 = __float2bfloat16(v.x), h1 = __float2bfloat16(v.y);
    __nv_bfloat16 h2 = __float2bfloat16(v.z), h3 = __float2bfloat16(v.w);
    ushort4 ph, pl;
    ph.x = __bfloat16_as_ushort(h0); ph.y = __bfloat16_as_ushort(h1);
    ph.z = __bfloat16_as_ushort(h2); ph.w = __bfloat16_as_ushort(h3);
    pl.x = __bfloat16_as_ushort(__float2bfloat16(v.x - __bfloat162float(h0)));
    pl.y = __bfloat16_as_ushort(__float2bfloat16(v.y - __bfloat162float(h1)));
    pl.z = __bfloat16_as_ushort(__float2bfloat16(v.z - __bfloat162float(h2)));
    pl.w = __bfloat16_as_ushort(__float2bfloat16(v.w - __bfloat162float(h3)));
    *(ushort4*)(&gXhi[r0 + ty][c0 + tx8 * 4]) = ph;
    *(ushort4*)(&gXlo[r0 + ty][c0 + tx8 * 4]) = pl;
    // x2 partial: reduce over the 8 threads sharing a row
    float s = v.x * v.x + v.y * v.y + v.z * v.z + v.w * v.w;
    s += __shfl_xor_sync(0xffffffffu, s, 1);
    s += __shfl_xor_sync(0xffffffffu, s, 2);
    s += __shfl_xor_sync(0xffffffffu, s, 4);
    if (tx8 == 0) atomicAdd(&gX2[r0 + ty], s);
    // smem tile for transpose
    tile[ty][tx8 * 4 + 0] = v.x;
    tile[ty][tx8 * 4 + 1] = v.y;
    tile[ty][tx8 * 4 + 2] = v.z;
    tile[ty][tx8 * 4 + 3] = v.w;
    __syncthreads();
    // transposed: thread -> col c = c0 + (t>>3), rows quad (t&7)*4
    int cc = t >> 3, rq = (t & 7) * 4;
    float w0 = tile[rq + 0][cc], w1 = tile[rq + 1][cc];
    float w2 = tile[rq + 2][cc], w3 = tile[rq + 3][cc];
    __nv_bfloat16 g0 = __float2bfloat16(w0), g1 = __float2bfloat16(w1);
    __nv_bfloat16 g2 = __float2bfloat16(w2), g3 = __float2bfloat16(w3);
    ushort4 qh, ql;
    qh.x = __bfloat16_as_ushort(g0); qh.y = __bfloat16_as_ushort(g1);
    qh.z = __bfloat16_as_ushort(g2); qh.w = __bfloat16_as_ushort(g3);
    ql.x = __bfloat16_as_ushort(__float2bfloat16(w0 - __bfloat162float(g0)));
    ql.y = __bfloat16_as_ushort(__float2bfloat16(w1 - __bfloat162float(g1)));
    ql.z = __bfloat16_as_ushort(__float2bfloat16(w2 - __bfloat162float(g2)));
    ql.w = __bfloat16_as_ushort(__float2bfloat16(w3 - __bfloat162float(g3)));
    *(ushort4*)(&gXThi[c0 + cc][r0 + rq]) = qh;
    *(ushort4*)(&gXTlo[c0 + cc][r0 + rq]) = ql;
}

// ---------------- per-k setup ----------------
__global__ void setup_kernel(const float* __restrict__ MU, const float* __restrict__ A,
                             const float* __restrict__ log_D, const float* __restrict__ PI_logits) {
    int k = blockIdx.x, t = threadIdx.x;
    __shared__ float sred[256];
    __shared__ float sPIk;
    if (t == 0) {
        float mx = -1e30f;
        for (int j = 0; j < KK; ++j) mx = fmaxf(mx, PI_logits[j]);
        float s = 0.f;
        for (int j = 0; j < KK; ++j) s += expf(PI_logits[j] - mx);
        sPIk = expf(PI_logits[k] - mx) / s;
    }
    float ld0 = log_D[(size_t)k * DD];
    float iD = expf(-ld0);
    float s2 = expf(ld0);
    float muSqAcc = 0.f;
    for (int d = t; d < DD; d += 256) {
        float mu = MU[(size_t)k * DD + d];
        __nv_bfloat16 h = __float2bfloat16(mu);
        gWThi[k][d] = h;
        gWTlo[k][d] = __float2bfloat16(mu - __bfloat162float(h));
        muSqAcc += mu * mu;
    }
    float bmuAcc = 0.f;
    {
        int l = t & 15;
        for (int d = t >> 4; d < DD; d += 16) {
            float a = A[((size_t)k * DD + d) * LL + l];
            __nv_bfloat16 h = __float2bfloat16(a);
            gWThi[32 + k * 16 + l][d] = h;
            gWTlo[32 + k * 16 + l][d] = __float2bfloat16(a - __bfloat162float(h));
            bmuAcc += MU[(size_t)k * DD + d] * a;
        }
    }
    int li = t >> 4, mi = t & 15;
    float ATAacc = 0.f;
    __shared__ float sA[16][16];
    for (int d0 = 0; d0 < DD; d0 += 16) {
        __syncthreads();
        sA[li][mi] = A[((size_t)k * DD + d0 + li) * LL + mi];
        __syncthreads();
        #pragma unroll
        for (int dd = 0; dd < 16; ++dd) ATAacc += sA[dd][li] * sA[dd][mi];
    }
    float muSqK = block_reduce_sum(muSqAcc, sred);
    __shared__ float sbm[16][17];
    sbm[t & 15][t >> 4] = bmuAcc;
    __syncthreads();
    if (t < 16) {
        float s = 0.f;
        for (int g = 0; g < 16; ++g) s += sbm[t][g];
        gbmu[k][t] = s;
    }
    __shared__ float aug[16][32];
    __shared__ float sfac[16];
    __shared__ int spiv;
    __shared__ float slogdet;
    if (t == 0) slogdet = 0.f;
    __syncthreads();
    aug[li][mi]      = iD * ATAacc + (li == mi ? 1.f : 0.f);
    aug[li][16 + mi] = (li == mi ? 1.f : 0.f);
    block_invert16(aug, &slogdet, sfac, &spiv);
    giL[k][li][mi] = aug[li][16 + mi];
    float logdetL = slogdet;
    __syncthreads();
    aug[li][mi]      = ATAacc + (li == mi ? s2 : 0.f);
    aug[li][16 + mi] = (li == mi ? 1.f : 0.f);
    block_invert16(aug, nullptr, sfac, &spiv);
    gInvM[k][li][mi] = aug[li][16 + mi];
    if (t == 0) {
        gmuSq[k] = muSqK;
        giD[k] = iD;
        gs2[k] = s2;
        gck[k] = sPIk - 0.5f * ((float)DD * LOG2PI_F + logdetL + (float)DD * ld0);
    }
}

// ---------------- mma.sync bf16x3 GEMM, 128x128 CTA tile ----------------
// 8 warps (2m x 4n), warp tile 64x32, K-chunk 32, double-buffered smem.
#define SROW 40
#define OFF_AHI 0
#define OFF_ALO 10240
#define OFF_BHI 20480
#define OFF_BLO 30720
#define BUFSZ   40960

__global__ void __launch_bounds__(256, 2) mma_gemm128(
    const __nv_bfloat16* __restrict__ Ahi, const __nv_bfloat16* __restrict__ Alo, int lda,
    const __nv_bfloat16* __restrict__ Bhi, const __nv_bfloat16* __restrict__ Blo, int ldb,
    float* __restrict__ C, int ldc, int zstride, int kLen)
{
    extern __shared__ __align__(128) char ds[];
    const uint32_t sbase = s2u(ds);
    const int t = threadIdx.x, lane = t & 31, w = t >> 5;
    const int wm = w & 1, wn = w >> 1;
    const int m0 = blockIdx.x * 128;
    const int n0 = blockIdx.y * 128;
    const int kBeg = blockIdx.z * kLen;
    const int nCh = kLen >> 5;
    C += (size_t)blockIdx.z * zstride;

    // load geometry: per array 512 uint4 slots; slots t and t+256
    const int row0 = t >> 2, q = (t & 3) * 8, row1 = row0 + 64;
    const size_t gA0 = (size_t)(m0 + row0) * lda + kBeg + q;
    const size_t gA1 = (size_t)(m0 + row1) * lda + kBeg + q;
    const size_t gB0 = (size_t)(n0 + row0) * ldb + kBeg + q;
    const size_t gB1 = (size_t)(n0 + row1) * ldb + kBeg + q;
    const int s0 = (row0 * SROW + q) * 2;
    const int s1 = (row1 * SROW + q) * 2;

    const int aoff = (wm * 64 + (lane & 15)) * SROW + ((lane >> 4) << 3);
    const int boff = (wn * 32 + (lane & 15)) * SROW + ((lane >> 4) << 3);

    float acc[4][4][4] = {};
    uint4 pAh0, pAh1, pAl0, pAl1, pBh0, pBh1, pBl0, pBl1;

    // preload chunk 0
    pAh0 = *(const uint4*)(Ahi + gA0); pAh1 = *(const uint4*)(Ahi + gA1);
    pAl0 = *(const uint4*)(Alo + gA0); pAl1 = *(const uint4*)(Alo + gA1);
    pBh0 = *(const uint4*)(Bhi + gB0); pBh1 = *(const uint4*)(Bhi + gB1);
    pBl0 = *(const uint4*)(Blo + gB0); pBl1 = *(const uint4*)(Blo + gB1);
    *(uint4*)(ds + OFF_AHI + s0) = pAh0; *(uint4*)(ds + OFF_AHI + s1) = pAh1;
    *(uint4*)(ds + OFF_ALO + s0) = pAl0; *(uint4*)(ds + OFF_ALO + s1) = pAl1;
    *(uint4*)(ds + OFF_BHI + s0) = pBh0; *(uint4*)(ds + OFF_BHI + s1) = pBh1;
    *(uint4*)(ds + OFF_BLO + s0) = pBl0; *(uint4*)(ds + OFF_BLO + s1) = pBl1;
    __syncthreads();

    int buf = 0;
    for (int ch = 0; ch < nCh; ++ch) {
        if (ch + 1 < nCh) {
            int kk = (ch + 1) * 32;
            pAh0 = *(const uint4*)(Ahi + gA0 + kk); pAh1 = *(const uint4*)(Ahi + gA1 + kk);
            pAl0 = *(const uint4*)(Alo + gA0 + kk); pAl1 = *(const uint4*)(Alo + gA1 + kk);
            pBh0 = *(const uint4*)(Bhi + gB0 + kk); pBh1 = *(const uint4*)(Bhi + gB1 + kk);
            pBl0 = *(const uint4*)(Blo + gB0 + kk); pBl1 = *(const uint4*)(Blo + gB1 + kk);
        }
        const uint32_t bA_h = sbase + buf * BUFSZ + OFF_AHI;
        const uint32_t bA_l = sbase + buf * BUFSZ + OFF_ALO;
        const uint32_t bB_h = sbase + buf * BUFSZ + OFF_BHI;
        const uint32_t bB_l = sbase + buf * BUFSZ + OFF_BLO;
        #pragma unroll
        for (int k0 = 0; k0 < 32; k0 += 16) {
            uint32_t bh[2][4], bl[2][4];
            #pragma unroll
            for (int p = 0; p < 2; ++p) {
                ldm4(bh[p], bB_h + (boff + p * 16 * SROW + k0) * 2);
                ldm4(bl[p], bB_l + (boff + p * 16 * SROW + k0) * 2);
            }
            #pragma unroll
            for (int mf = 0; mf < 4; ++mf) {
                uint32_t ah[4], al[4];
                ldm4(ah, bA_h + (aoff + mf * 16 * SROW + k0) * 2);
                ldm4(al, bA_l + (aoff + mf * 16 * SROW + k0) * 2);
                #pragma unroll
                for (int nf = 0; nf < 4; ++nf) {
                    int p = nf >> 1, o = nf & 1;
                    mma16816(acc[mf][nf], ah, bh[p][o], bh[p][2 + o]);
                    mma16816(acc[mf][nf], ah, bl[p][o], bl[p][2 + o]);
                    mma16816(acc[mf][nf], al, bh[p][o], bh[p][2 + o]);
                }
            }
        }
        if (ch + 1 < nCh) {
            char* dn = ds + (buf ^ 1) * BUFSZ;
            *(uint4*)(dn + OFF_AHI + s0) = pAh0; *(uint4*)(dn + OFF_AHI + s1) = pAh1;
            *(uint4*)(dn + OFF_ALO + s0) = pAl0; *(uint4*)(dn + OFF_ALO + s1) = pAl1;
            *(uint4*)(dn + OFF_BHI + s0) = pBh0; *(uint4*)(dn + OFF_BHI + s1) = pBh1;
            *(uint4*)(dn + OFF_BLO + s0) = pBl0; *(uint4*)(dn + OFF_BLO + s1) = pBl1;
            __syncthreads();
            buf ^= 1;
        }
    }

    const int gid = lane >> 2, tid = lane & 3;
    #pragma unroll
    for (int mf = 0; mf < 4; ++mf) {
        #pragma unroll
        for (int nf = 0; nf < 4; ++nf) {
            int row = m0 + wm * 64 + mf * 16 + gid;
            int col = n0 + wn * 32 + nf * 8 + tid * 2;
            float* c0 = C + (size_t)row * ldc + col;
            float* c1 = C + (size_t)(row + 8) * ldc + col;
            *(float2*)c0 = make_float2(acc[mf][nf][0], acc[mf][nf][1]);
            *(float2*)c1 = make_float2(acc[mf][nf][2], acc[mf][nf][3]);
        }
    }
}

// ---------------- E-step epilogue ----------------
__global__ void __launch_bounds__(256) estep_epilogue() {
    __shared__ float siLs[KK * 272];
    __shared__ float sbmu_[KK][LL];
    __shared__ float smuSq_[KK];
    __shared__ float siD_[KK];
    __shared__ float sck_[KK];
    __shared__ float sll[8][32];
    int t = threadIdx.x;
    for (int idx = t; idx < KK * 256; idx += 256) {
        int kk = idx >> 8, rem = idx & 255;
        siLs[kk * 272 + (rem >> 4) * 17 + (rem & 15)] = (&giL[0][0][0])[idx];
    }
    for (int idx = t; idx < KK * LL; idx += 256) (&sbmu_[0][0])[idx] = (&gbmu[0][0])[idx];
    if (t < KK) { smuSq_[t] = gmuSq[t]; sck_[t] = gck[t]; siD_[t] = giD[t]; }
    __syncthreads();

    int warp = t >> 5, lane = t & 31;
    int n = blockIdx.x * 8 + warp;
    const float* Crow = &gC[n][0];
    float x2 = gX2[n];
    #pragma unroll 1
    for (int it = 0; it < 16; ++it) {
        int k = it * 2 + (lane >> 4);
        int gl = lane & 15;
        float yv = Crow[32 + k * 16 + gl] - sbmu_[k][gl];
        float z = 0.f;
        const float* ilr = &siLs[k * 272 + gl * 17];
        #pragma unroll
        for (int m = 0; m < 16; ++m) {
            float ym = __shfl_sync(0xffffffffu, yv, (lane & 16) | m);
            z += ilr[m] * ym;
        }
        float t2 = z * yv;
        #pragma unroll
        for (int off = 8; off > 0; off >>= 1) t2 += __shfl_xor_sync(0xffffffffu, t2, off);
        if (gl == 0) {
            float iD = siD_[k];
            float term1 = iD * (x2 - 2.f * Crow[k] + smuSq_[k]);
            sll[warp][k] = sck_[k] - 0.5f * term1 + 0.5f * iD * iD * t2;
        }
    }
    __syncwarp();
    float llk = sll[warp][lane];
    float mx = llk;
    #pragma unroll
    for (int off = 16; off > 0; off >>= 1) mx = fmaxf(mx, __shfl_xor_sync(0xffffffffu, mx, off));
    float e = expf(llk - mx);
    float s = e;
    #pragma unroll
    for (int off = 16; off > 0; off >>= 1) s += __shfl_xor_sync(0xffffffffu, s, off);
    float r = e / s;
    float* Mrow = &gM2[n][0];
    Mrow[lane] = r;
    Mrow[544 + lane] = r * x2;
    Mrow[576 + lane] = 0.f;
    Mrow[608 + lane] = 0.f;
    #pragma unroll
    for (int it = 0; it < 16; ++it) {
        int j = it * 32 + lane;
        float rk = __shfl_sync(0xffffffffu, r, j >> 4);
        Mrow[32 + j] = rk * Crow[32 + j];
    }
}

// ---------------- transpose-split M2 + fused column sums ----------------
__global__ void __launch_bounds__(256) tsplit_m2_kernel() {
    __shared__ float tile[32][33];
    int t = threadIdx.x;
    int tx = t & 31, ty = t >> 5;
    int c0 = blockIdx.x * 32;   // along M2W
    int r0 = blockIdx.y * 32;   // along NN
    #pragma unroll
    for (int j = 0; j < 32; j += 8)
        tile[ty + j][tx] = gM2[r0 + ty + j][c0 + tx];
    __syncthreads();
    #pragma unroll
    for (int j = 0; j < 32; j += 8) {
        int wcol = c0 + ty + j;
        int h = r0 + tx;
        float v = tile[tx][ty + j];
        __nv_bfloat16 hi = __float2bfloat16(v);
        gM2Thi[wcol][h] = hi;
        gM2Tlo[wcol][h] = __float2bfloat16(v - __bfloat162float(hi));
    }
    // fused column sums (first warp)
    if (t < 32) {
        int col = c0 + t;
        if (col < 576) {
            float s = 0.f;
            #pragma unroll
            for (int rr = 0; rr < 32; ++rr) s += tile[rr][t];
            if (col < 32)       atomicAdd(&grsum[col], s);
            else if (col < 544) atomicAdd(&gG[0][0] + (col - 32), s);
            else                atomicAdd(&grx2[col - 544], s);
        }
    }
}

// ---------------- finalize: sum 8 slabs, mu + SiAi ----------------
__global__ void __launch_bounds__(256) finalize_kernel(float* __restrict__ outMu) {
    __shared__ float sums[8][544];
    int t = threadIdx.x, warp = t >> 5, lane = t & 31;
    int d = blockIdx.x * 8 + warp;
    const float* base = &gSiAiP[d][0][0];
    for (int c = lane; c < 544; c += 32) {
        float s = 0.f;
        #pragma unroll
        for (int j = 0; j < 8; ++j) s += base[j * M2W + c];
        sums[warp][c] = s;
    }
    __syncwarp();
    // mu for all 32 k (this d)
    if (lane < 32) {
        int k = lane;
        float mu = sums[warp][k] / grsum[k];
        gmu[k][d] = mu;
        outMu[k * DD + d] = mu;
    }
    __syncwarp();
    for (int c = 32 + lane; c < 544; c += 32) {
        int k = (c - 32) >> 4, l = (c - 32) & 15;
        float rs = grsum[k];
        float mu = sums[warp][k] / rs;
        gSiAi2[k][d][l] = (sums[warp][c] - mu * gG[k][l]) / rs;
    }
}

// ---------------- per-k M-step ----------------
__global__ void __launch_bounds__(256) mstep_kernel(const float* __restrict__ A,
                                                    float* __restrict__ outA,
                                                    float* __restrict__ outLogD,
                                                    float* __restrict__ outPI) {
    int k = blockIdx.x, t = threadIdx.x;
    int li = t >> 4, mi = t & 15;
    __shared__ float sS[16][16];
    __shared__ float sAs[16][16];
    float acc = 0.f;
    for (int d0 = 0; d0 < DD; d0 += 16) {
        __syncthreads();
        sAs[li][mi] = A[((size_t)k * DD + d0 + li) * LL + mi];
        sS [li][mi] = gSiAi2[k][d0 + li][mi];
        __syncthreads();
        #pragma unroll
        for (int dd = 0; dd < 16; ++dd) acc += sAs[dd][li] * sS[dd][mi];
    }
    __shared__ float sATS[16][16];
    __shared__ float siM[16][16];
    __syncthreads();
    sATS[li][mi] = acc;
    siM[li][mi] = gInvM[k][li][mi];
    __syncthreads();
    float Tv = 0.f;
    #pragma unroll
    for (int j = 0; j < 16; ++j) Tv += siM[li][j] * sATS[j][mi];
    __shared__ float aug[16][32];
    __shared__ float sfac[16];
    __shared__ int spiv;
    aug[li][mi]      = Tv + (li == mi ? gs2[k] : 0.f);
    aug[li][16 + mi] = (li == mi ? 1.f : 0.f);
    block_invert16(aug, nullptr, sfac, &spiv);
    __shared__ float sW2[16][16];
    sW2[li][mi] = aug[li][16 + mi];
    __syncthreads();
    float t1acc = 0.f;
    for (int d0 = 0; d0 < DD; d0 += 16) {
        __syncthreads();
        sS[li][mi] = gSiAi2[k][d0 + li][mi];
        __syncthreads();
        float an = 0.f, sim = 0.f;
        #pragma unroll
        for (int m = 0; m < 16; ++m) {
            float sv = sS[li][m];
            an  += sv * sW2[m][mi];
            sim += sv * siM[m][mi];
        }
        outA[((size_t)k * DD + d0 + li) * LL + mi] = an;
        t1acc += an * sim;
    }
    float msq = 0.f;
    for (int d = t; d < DD; d += 256) { float m = gmu[k][d]; msq += m * m; }
    __shared__ float sred[256];
    float t1   = block_reduce_sum(t1acc, sred);
    float msqs = block_reduce_sum(msq, sred);
    __shared__ float sld;
    if (t == 0) {
        float rs = grsum[k];
        float traceS = (grx2[k] - rs * msqs) / rs;
        float sig2 = (traceS - t1) / (float)DD;
        sld = logf(sig2);
        float tot = 0.f;
        for (int j = 0; j < KK; ++j) tot += grsum[j];
        outPI[k] = logf(grsum[k] / tot);
    }
    __syncthreads();
    float ldv = sld;
    for (int d = t; d < DD; d += 256) outLogD[k * DD + d] = ldv;
}

// ---------------- launch ----------------
extern "C" void kernel_launch(void* const* d_in, const int* in_sizes, int n_in,
                              void* d_out, int out_size) {
    const float* x   = (const float*)d_in[0];
    const float* MU  = (const float*)d_in[1];
    const float* A   = (const float*)d_in[2];
    const float* lD  = (const float*)d_in[3];
    const float* PIl = (const float*)d_in[4];
    float* out = (float*)d_out;
    float* outMu   = out;
    float* outA    = out + KK * DD;
    float* outLogD = out + KK * DD + KK * DD * LL;
    float* outPI   = out + KK * DD + KK * DD * LL + KK * DD;

    const int DSMEM = 2 * BUFSZ;   // 81920
    cudaFuncSetAttribute(mma_gemm128, cudaFuncAttributeMaxDynamicSharedMemorySize, DSMEM);

    __nv_bfloat16 *pXhi, *pXlo, *pXThi, *pXTlo, *pWThi, *pWTlo, *pM2Thi, *pM2Tlo;
    float *pC, *pSiAiP;
    cudaGetSymbolAddress((void**)&pXhi,   gXhi);
    cudaGetSymbolAddress((void**)&pXlo,   gXlo);
    cudaGetSymbolAddress((void**)&pXThi,  gXThi);
    cudaGetSymbolAddress((void**)&pXTlo,  gXTlo);
    cudaGetSymbolAddress((void**)&pWThi,  gWThi);
    cudaGetSymbolAddress((void**)&pWTlo,  gWTlo);
    cudaGetSymbolAddress((void**)&pM2Thi, gM2Thi);
    cudaGetSymbolAddress((void**)&pM2Tlo, gM2Tlo);
    cudaGetSymbolAddress((void**)&pC,     gC);
    cudaGetSymbolAddress((void**)&pSiAiP, gSiAiP);

    zero_kernel<<<1024, 256>>>();
    xprep_kernel<<<dim3(DD / 32, NN / 32), 256>>>(x);
    setup_kernel<<<KK, 256>>>(MU, A, lD, PIl);
    // GEMM1: C[16384,640] = X @ W^T
    mma_gemm128<<<dim3(NN / 128, WPAD / 128, 1), 256, DSMEM>>>(
        pXhi, pXlo, DD, pWThi, pWTlo, DD, pC, WPAD, 0, DD);
    estep_epilogue<<<NN / 8, 256>>>();
    tsplit_m2_kernel<<<dim3(M2W / 32, NN / 32), 256>>>();
    // GEMM_d: 8 k-split slabs, non-atomic writes into gSiAiP[d][z][col]
    mma_gemm128<<<dim3(DD / 128, M2W / 128, 8), 256, DSMEM>>>(
        pXThi, pXTlo, NN, pM2Thi, pM2Tlo, NN, pSiAiP, 8 * M2W, M2W, NN / 8);
    finalize_kernel<<<DD / 8, 256>>>(outMu);
    mstep_kernel<<<KK, 256>>>(A, outA, outLogD, outPI);
}